// round 12
// baseline (speedup 1.0000x reference)
#include <cuda_runtime.h>
#include <cuda_bf16.h>
#include <math.h>
#include <stdint.h>

// Problem constants
#define Bv    32
#define Nv    4096
#define INPv  512
#define ROWSv (Bv*Nv)   // 131072

// ---------------- scratch (static device globals; no allocs allowed) ----------------
__device__ __align__(16) float g_k[16777216];      // bf16 image [ROWS][256]
__device__ __align__(16) float g_v[16777216];      // bf16 image [ROWS][256]
__device__ __align__(16) uint16_t g_xh[67108864];  // bf16 image of X, MMA-swizzled [row][1024B]
__device__ __align__(16) uint16_t g_wth[262144];   // bf16 image of fused W^T [n][1024B]
__device__ __align__(16) float g_stats[262144];    // [ROWS][2] mean,rstd
__device__ __align__(16) float g_wsum[512];        // colsum of [Wk|Wv]
__device__ __align__(16) float g_wihT[196608];     // k-major wih^T [256][768]
__device__ __align__(16) float g_whhT[196608];     // k-major whh^T [256][768]
__device__ __align__(16) float g_sln[65536];
__device__ __align__(16) float g_q[65536];
__device__ __align__(16) float g_upd[65536];
__device__ __align__(16) float g_colsum[256];

__device__ __forceinline__ uint32_t smem_u32(const void* p) {
    uint32_t a;
    asm("{ .reg .u64 t; cvta.to.shared.u64 t, %1; cvt.u32.u64 %0, t; }" : "=r"(a) : "l"(p));
    return a;
}
__device__ __forceinline__ void cpasync16(uint32_t d, const void* g) {
    asm volatile("cp.async.cg.shared.global [%0], [%1], 16;" :: "r"(d), "l"(g));
}
#define CP_COMMIT() asm volatile("cp.async.commit_group;" ::: "memory")

// image byte offset within a row for element k (k-pair permute + region rotation by row)
__device__ __forceinline__ int img_off(int k, int row) {
    int bblk = k >> 6;
    int c    = (k >> 4) & 3;
    int kk   = k & 15;
    int p    = kk >> 1;
    int slot = ((p & 3) << 1) | (p >> 2);
    int reg  = (c + row) & 3;
    return bblk * 128 + reg * 32 + slot * 4 + (kk & 1) * 2;
}

// ---------------- LN stats + bf16 swizzled image of X ----------------
__global__ void ln_stats_kernel(const float* __restrict__ X) {
    __shared__ __align__(16) uint16_t img[8][512];
    int warp = threadIdx.x >> 5, lane = threadIdx.x & 31;
    int row  = blockIdx.x * 8 + warp;
    const float* xr = X + (size_t)row * INPv;
    float4 v[4];
    float s = 0.f, s2 = 0.f;
#pragma unroll
    for (int j = 0; j < 4; j++) {
        v[j] = *(const float4*)(xr + lane * 4 + 128 * j);
        s  += v[j].x + v[j].y + v[j].z + v[j].w;
        s2 += v[j].x * v[j].x + v[j].y * v[j].y + v[j].z * v[j].z + v[j].w * v[j].w;
    }
#pragma unroll
    for (int off = 16; off; off >>= 1) {
        s  += __shfl_down_sync(0xffffffffu, s,  off);
        s2 += __shfl_down_sync(0xffffffffu, s2, off);
    }
    if (!lane) {
        float m   = s * (1.f / INPv);
        float var = s2 * (1.f / INPv) - m * m;
        g_stats[row * 2]     = m;
        g_stats[row * 2 + 1] = rsqrtf(var + 1e-5f);
    }
#pragma unroll
    for (int j = 0; j < 4; j++) {
        int k0 = lane * 4 + 128 * j;
        float vals[4] = {v[j].x, v[j].y, v[j].z, v[j].w};
#pragma unroll
        for (int t = 0; t < 2; t++) {
            int k = k0 + 2 * t;
            __nv_bfloat162 h2 = __floats2bfloat162_rn(vals[2 * t], vals[2 * t + 1]);
            *(uint32_t*)((char*)img[warp] + img_off(k, row)) = *(uint32_t*)&h2;
        }
    }
    __syncwarp();
    uint4* srcp = (uint4*)img[warp];
    uint4* dstp = (uint4*)(g_xh + (size_t)row * 512);
    dstp[lane]      = srcp[lane];
    dstp[lane + 32] = srcp[lane + 32];
}

// ---------------- column sums of Wk|Wv ----------------
__global__ void wsum_kernel(const float* __restrict__ Wk, const float* __restrict__ Wv) {
    __shared__ float red[4][64];
    int b = blockIdx.x;
    int c0 = b * 64;
    int col = threadIdx.x & 63, part = threadIdx.x >> 6;
    const float* W = (c0 < 256) ? Wk : Wv;
    int cc = (c0 & 255) + col;
    float s = 0.f;
    for (int k = part * 128; k < part * 128 + 128; k++) s += W[k * 256 + cc];
    red[part][col] = s;
    __syncthreads();
    if (threadIdx.x < 64) {
        g_wsum[c0 + threadIdx.x] = red[0][threadIdx.x] + red[1][threadIdx.x]
                                 + red[2][threadIdx.x] + red[3][threadIdx.x];
    }
}

// ---------------- transposed fused-W bf16 image: g_wth[n][k-image] ----------------
__global__ void transpose_w_kernel(const float* __restrict__ Wk, const float* __restrict__ Wv) {
    __shared__ float t[32][33];
    int n0 = blockIdx.x * 32, k0 = blockIdx.y * 32;
    int tx = threadIdx.x, ty = threadIdx.y;     // (32, 8)
    const float* W = (n0 < 256) ? Wk : Wv;
    int col0 = n0 & 255;
#pragma unroll
    for (int j = 0; j < 4; j++) {
        int k = k0 + ty + 8 * j;
        t[ty + 8 * j][tx] = W[(size_t)k * 256 + col0 + tx];
    }
    __syncthreads();
#pragma unroll
    for (int j = 0; j < 4; j++) {
        int n = n0 + ty + 8 * j;
        int k = k0 + tx;
        __nv_bfloat16 h = __float2bfloat16(t[tx][ty + 8 * j]);
        g_wth[(size_t)n * 512 + (img_off(k, n) >> 1)] = *(uint16_t*)&h;
    }
}

// ---------------- transpose GRU weights to k-major [256][768] ----------------
__global__ void transpose_gru_kernel(const float* __restrict__ wih, const float* __restrict__ whh) {
    __shared__ float t[32][33];
    const float* src = blockIdx.z ? whh : wih;
    float* dst = blockIdx.z ? g_whhT : g_wihT;
    int r0 = blockIdx.x * 32, k0 = blockIdx.y * 32;
    int tx = threadIdx.x, ty = threadIdx.y;
#pragma unroll
    for (int j = 0; j < 4; j++)
        t[ty + 8 * j][tx] = src[(size_t)(r0 + ty + 8 * j) * 256 + k0 + tx];
    __syncthreads();
#pragma unroll
    for (int j = 0; j < 4; j++)
        dst[(size_t)(k0 + ty + 8 * j) * 768 + r0 + tx] = t[tx][ty + 8 * j];
}

// ---------------- bf16 mma.sync projection, triple-buffered ----------------
#define STG 16384   // 128 rows x 128 B per stage tile

__global__ __launch_bounds__(256, 2)
void proj_mma_kernel() {
    extern __shared__ char dsm[];
    uint32_t sb = smem_u32(dsm);
    int n0   = blockIdx.x * 128;
    int row0 = blockIdx.y * 128;
    int tid  = threadIdx.x;
    int wid  = tid >> 5, lane = tid & 31;
    int warp_m = wid >> 2, warp_n = wid & 3;
    int mb = warp_m * 64, nb = warp_n * 32;
    int grp = lane >> 2, q = lane & 3;
    int lr = tid >> 1, lh = tid & 1;

    float acc[4][4][4];
#pragma unroll
    for (int f = 0; f < 4; f++)
#pragma unroll
        for (int g = 0; g < 4; g++)
#pragma unroll
            for (int c = 0; c < 4; c++) acc[f][g][c] = 0.f;

    auto issue = [&](int s, int buf) {
        const char* srcA = (const char*)g_xh  + (size_t)(row0 + lr) * 1024 + s * 128 + lh * 64;
        const char* srcB = (const char*)g_wth + (size_t)(n0   + lr) * 1024 + s * 128 + lh * 64;
        uint32_t dA = sb + buf * STG       + lr * 128 + lh * 64;
        uint32_t dB = sb + (3 + buf) * STG + lr * 128 + lh * 64;
#pragma unroll
        for (int gi = 0; gi < 4; gi++) {
            cpasync16(dA + gi * 16, srcA + gi * 16);
            cpasync16(dB + gi * 16, srcB + gi * 16);
        }
    };

    issue(0, 0); CP_COMMIT();
    issue(1, 1); CP_COMMIT();

    for (int s = 0; s < 8; s++) {
        if (s < 7) asm volatile("cp.async.wait_group 1;" ::: "memory");
        else       asm volatile("cp.async.wait_group 0;" ::: "memory");
        __syncthreads();
        if (s < 6) { issue(s + 2, (s + 2) % 3); CP_COMMIT(); }

        int buf = s % 3;
        const char* As = dsm + buf * STG;
        const char* Bs = dsm + (3 + buf) * STG;
#pragma unroll
        for (int c = 0; c < 4; c++) {
            uint2 bfr[4];
#pragma unroll
            for (int g = 0; g < 4; g++) {
                int rn = nb + g * 8 + grp;
                bfr[g] = *(const uint2*)(Bs + rn * 128 + ((c + rn) & 3) * 32 + q * 8);
            }
#pragma unroll
            for (int f = 0; f < 4; f++) {
                int r0 = mb + f * 16 + grp;
                int r1 = r0 + 8;
                uint2 aa = *(const uint2*)(As + r0 * 128 + ((c + r0) & 3) * 32 + q * 8);
                uint2 ab = *(const uint2*)(As + r1 * 128 + ((c + r1) & 3) * 32 + q * 8);
#pragma unroll
                for (int g = 0; g < 4; g++) {
                    asm volatile(
                        "mma.sync.aligned.m16n8k16.row.col.f32.bf16.bf16.f32 "
                        "{%0,%1,%2,%3}, {%4,%5,%6,%7}, {%8,%9}, {%0,%1,%2,%3};"
                        : "+f"(acc[f][g][0]), "+f"(acc[f][g][1]),
                          "+f"(acc[f][g][2]), "+f"(acc[f][g][3])
                        : "r"(aa.x), "r"(ab.x), "r"(aa.y), "r"(ab.y),
                          "r"(bfr[g].x), "r"(bfr[g].y));
                }
            }
        }
    }

    __nv_bfloat16* kh = (__nv_bfloat16*)g_k;
    __nv_bfloat16* vh = (__nv_bfloat16*)g_v;
#pragma unroll
    for (int f = 0; f < 4; f++) {
        int r0g = row0 + mb + f * 16 + grp;
        int r1g = r0g + 8;
        float m0 = g_stats[r0g * 2], s0 = g_stats[r0g * 2 + 1];
        float m1 = g_stats[r1g * 2], s1 = g_stats[r1g * 2 + 1];
        float mr0 = m0 * s0, mr1 = m1 * s1;
#pragma unroll
        for (int g = 0; g < 4; g++) {
            int nglob = n0 + nb + g * 8 + q * 2;
            float ws0 = g_wsum[nglob], ws1 = g_wsum[nglob + 1];
            __nv_bfloat162 o0 = __floats2bfloat162_rn(
                s0 * acc[f][g][0] - mr0 * ws0, s0 * acc[f][g][1] - mr0 * ws1);
            __nv_bfloat162 o1 = __floats2bfloat162_rn(
                s1 * acc[f][g][2] - mr1 * ws0, s1 * acc[f][g][3] - mr1 * ws1);
            if (nglob < 256) {
                *(__nv_bfloat162*)(kh + (size_t)r0g * 256 + nglob) = o0;
                *(__nv_bfloat162*)(kh + (size_t)r1g * 256 + nglob) = o1;
            } else {
                *(__nv_bfloat162*)(vh + (size_t)r0g * 256 + nglob - 256) = o0;
                *(__nv_bfloat162*)(vh + (size_t)r1g * 256 + nglob - 256) = o1;
            }
        }
    }
}

// ---------------- row LN over 8 rows x 256 (512 threads), src/dst in smem ----------------
__device__ __forceinline__ void row_ln8(const float* src, float* dst, float* s_red, int t) {
    int r = t >> 6, l64 = t & 63;
    float s = 0.f, s2 = 0.f;
#pragma unroll
    for (int j = 0; j < 4; j++) {
        float v = src[r * 256 + l64 + 64 * j];
        s += v; s2 += v * v;
    }
#pragma unroll
    for (int off = 16; off; off >>= 1) {
        s  += __shfl_down_sync(0xffffffffu, s,  off);
        s2 += __shfl_down_sync(0xffffffffu, s2, off);
    }
    int w = t >> 5;
    if ((t & 31) == 0) { s_red[w * 2] = s; s_red[w * 2 + 1] = s2; }
    __syncthreads();
    if (t < 8) {
        float ts = s_red[4 * t]     + s_red[4 * t + 2];
        float t2 = s_red[4 * t + 1] + s_red[4 * t + 3];
        float m = ts * (1.f / 256.f), var = t2 * (1.f / 256.f) - m * m;
        s_red[32 + 2 * t]     = m;
        s_red[32 + 2 * t + 1] = rsqrtf(var + 1e-5f);
    }
    __syncthreads();
    for (int i = t; i < 2048; i += 512) {
        int rr = i >> 8;
        dst[i] = (src[i] - s_red[32 + 2 * rr]) * s_red[33 + 2 * rr];
    }
    __syncthreads();
}

// q = sln @ Wq, sln in smem; also store sln to global
__device__ __forceinline__ void q_and_store(const float* s_sln, const float* __restrict__ Wq,
                                            int b, int t) {
    for (int i = t; i < 2048; i += 512) g_sln[b * 2048 + i] = s_sln[i];
    int c = t & 255, rg = t >> 8;
    float acc[4] = {0.f, 0.f, 0.f, 0.f};
    for (int k = 0; k < 256; k += 4) {
        float w0 = Wq[(k + 0) * 256 + c];
        float w1v = Wq[(k + 1) * 256 + c];
        float w2v = Wq[(k + 2) * 256 + c];
        float w3 = Wq[(k + 3) * 256 + c];
#pragma unroll
        for (int i = 0; i < 4; i++) {
            const float4 a = *(const float4*)(s_sln + (rg * 4 + i) * 256 + k);
            acc[i] += a.x * w0 + a.y * w1v + a.z * w2v + a.w * w3;
        }
    }
#pragma unroll
    for (int i = 0; i < 4; i++)
        g_q[b * 2048 + (rg * 4 + i) * 256 + c] = acc[i];
    // zero accumulators for next attn
    for (int i = t; i < 2048; i += 512) g_upd[b * 2048 + i] = 0.f;
    if (t < 8) g_colsum[b * 8 + t] = 0.f;
}

// ---------------- prologue: slots init + LN + q ----------------
__global__ __launch_bounds__(512)
void slot_init_kernel(const float* __restrict__ noise, const float* __restrict__ mu,
                      const float* __restrict__ ls, const float* __restrict__ Wq) {
    __shared__ float s_h[2048];
    __shared__ float s_sln[2048];
    __shared__ float s_red[64];
    int b = blockIdx.x, t = threadIdx.x;
    for (int i = t; i < 2048; i += 512) {
        int d = i & 255;
        s_h[i] = mu[d] + __expf(ls[d]) * noise[b * 2048 + i];
    }
    __syncthreads();
    row_ln8(s_h, s_sln, s_red, t);
    q_and_store(s_sln, Wq, b, t);
}

// ---------------- fused attention + updates (bf16 k/v) ----------------
__global__ __launch_bounds__(256)
void attn_upd_kernel() {
    __shared__ __align__(16) float qs[2048];
    __shared__ float ps[128 * 8];
    int b  = blockIdx.y;
    int n0 = blockIdx.x * 128;
    int tid = threadIdx.x;
    int warp = tid >> 5, lane = tid & 31;
    const __nv_bfloat16* kh = (const __nv_bfloat16*)g_k;
    const __nv_bfloat16* vh = (const __nv_bfloat16*)g_v;

    for (int i = tid; i < 2048; i += 256) qs[i] = g_q[(size_t)b * 2048 + i];
    __syncthreads();

    const float scale = 0.0625f;
    float csum[8] = {};
#pragma unroll
    for (int g = 0; g < 4; g++) {
        int nb = warp * 16 + g * 4;
        const uint32_t* kp = (const uint32_t*)(kh + ((size_t)(b * Nv + n0 + nb)) * 256);
        float part[4][8] = {};
#pragma unroll
        for (int j = 0; j < 4; j++) {
            int pi = lane + 32 * j;
            float2 kv[4];
#pragma unroll
            for (int i = 0; i < 4; i++)
                kv[i] = __bfloat1622float2(*(const __nv_bfloat162*)&kp[i * 128 + pi]);
#pragma unroll
            for (int s = 0; s < 8; s++) {
                float2 qv = *(const float2*)(qs + s * 256 + 2 * pi);
#pragma unroll
                for (int i = 0; i < 4; i++)
                    part[i][s] += kv[i].x * qv.x + kv[i].y * qv.y;
            }
        }
#pragma unroll
        for (int i = 0; i < 4; i++)
#pragma unroll
            for (int s = 0; s < 8; s++)
#pragma unroll
                for (int off = 16; off; off >>= 1)
                    part[i][s] += __shfl_down_sync(0xffffffffu, part[i][s], off);
        if (lane == 0) {
#pragma unroll
            for (int i = 0; i < 4; i++) {
                float m = -1e30f;
#pragma unroll
                for (int s = 0; s < 8; s++) m = fmaxf(m, part[i][s] * scale);
                float e[8], sum = 0.f;
#pragma unroll
                for (int s = 0; s < 8; s++) { e[s] = __expf(part[i][s] * scale - m); sum += e[s]; }
                float inv = 1.f / sum;
                int nl = warp * 16 + g * 4 + i;
#pragma unroll
                for (int s = 0; s < 8; s++) {
                    float p = e[s] * inv + 1e-8f;
                    ps[nl * 8 + s] = p;
                    csum[s] += p;
                }
            }
        }
    }
    if (lane == 0) {
#pragma unroll
        for (int s = 0; s < 8; s++) atomicAdd(&g_colsum[b * 8 + s], csum[s]);
    }
    __syncthreads();

    int d = tid;
    float acc[8] = {};
    const __nv_bfloat16* vb = vh + ((size_t)(b * Nv + n0)) * 256;
#pragma unroll 4
    for (int n = 0; n < 128; n++) {
        float vv = __bfloat162float(vb[(size_t)n * 256 + d]);
#pragma unroll
        for (int s = 0; s < 8; s++) acc[s] += ps[n * 8 + s] * vv;
    }
#pragma unroll
    for (int s = 0; s < 8; s++) atomicAdd(&g_upd[(b * 8 + s) * 256 + d], acc[s]);
}

// ---------------- fused slot tail: GRU gemms + combine + LN + MLP + next LN/q ----------------
// 32 blocks (one batch each) x 512 threads. All row-local.
#define TAIL_SMEM (24640 * 4)

__global__ __launch_bounds__(512, 1)
void slot_tail_kernel(const float* __restrict__ bih, const float* __restrict__ bhh,
                      const float* __restrict__ w1, const float* __restrict__ b1,
                      const float* __restrict__ w2, const float* __restrict__ b2,
                      const float* __restrict__ Wq, float* __restrict__ dout, int last) {
    extern __shared__ float sm[];
    float* s_upd = sm;            // 2048 (later reused as final-slot buffer)
    float* s_sln = sm + 2048;     // 2048
    float* s_gx  = sm + 4096;     // 6144
    float* s_gh  = sm + 10240;    // 6144
    float* s_h   = sm + 16384;    // 2048
    float* s_y   = sm + 18432;    // 2048
    float* s_h1  = sm + 20480;    // 4096
    float* s_red = sm + 24576;    // 64
    int b = blockIdx.x, t = threadIdx.x;

    // load upd (normalized by colsum) and sln
    for (int i = t; i < 2048; i += 512) {
        int r = i >> 8;
        s_upd[i] = g_upd[b * 2048 + i] / g_colsum[b * 8 + r];
        s_sln[i] = g_sln[b * 2048 + i];
    }
    __syncthreads();

    // gate GEMMs: gx = upd @ wihT + bih ; gh = sln @ whhT + bhh  (k-major weights)
#pragma unroll
    for (int jj = 0; jj < 3; jj++) {
        int job = t + 512 * jj;                    // 0..1535
        int isx = (job < 768);
        int c = isx ? job : job - 768;
        const float* WT = isx ? g_wihT : g_whhT;
        const float* A  = isx ? s_upd : s_sln;
        float bias = isx ? bih[c] : bhh[c];
        float acc[8];
#pragma unroll
        for (int r = 0; r < 8; r++) acc[r] = bias;
        for (int k = 0; k < 256; k += 4) {
            float w0 = WT[(k + 0) * 768 + c];
            float w1v = WT[(k + 1) * 768 + c];
            float w2v = WT[(k + 2) * 768 + c];
            float w3 = WT[(k + 3) * 768 + c];
#pragma unroll
            for (int r = 0; r < 8; r++) {
                const float4 a = *(const float4*)(A + r * 256 + k);
                acc[r] += a.x * w0 + a.y * w1v + a.z * w2v + a.w * w3;
            }
        }
        float* dst = isx ? s_gx : s_gh;
#pragma unroll
        for (int r = 0; r < 8; r++) dst[r * 768 + c] = acc[r];
    }
    __syncthreads();

    // GRU combine
    for (int i = t; i < 2048; i += 512) {
        int r = i >> 8, d = i & 255;
        float xr = s_gx[r * 768 + d],       hr = s_gh[r * 768 + d];
        float xz = s_gx[r * 768 + 256 + d], hz = s_gh[r * 768 + 256 + d];
        float xn = s_gx[r * 768 + 512 + d], hn = s_gh[r * 768 + 512 + d];
        float rg = 1.f / (1.f + __expf(-(xr + hr)));
        float zg = 1.f / (1.f + __expf(-(xz + hz)));
        float ng = tanhf(xn + rg * hn);
        s_h[i] = (1.f - zg) * ng + zg * s_sln[i];
    }
    __syncthreads();

    // y = LN(h)
    row_ln8(s_h, s_y, s_red, t);

    // h1 = relu(y @ w1 + b1)   (w1 k-major [256][512])
    {
        int c = t;
        float acc[8];
#pragma unroll
        for (int r = 0; r < 8; r++) acc[r] = b1[c];
        for (int k = 0; k < 256; k += 4) {
            float w0 = w1[(k + 0) * 512 + c];
            float w1v = w1[(k + 1) * 512 + c];
            float w2v = w1[(k + 2) * 512 + c];
            float w3 = w1[(k + 3) * 512 + c];
#pragma unroll
            for (int r = 0; r < 8; r++) {
                const float4 a = *(const float4*)(s_y + r * 256 + k);
                acc[r] += a.x * w0 + a.y * w1v + a.z * w2v + a.w * w3;
            }
        }
#pragma unroll
        for (int r = 0; r < 8; r++) s_h1[r * 512 + c] = fmaxf(acc[r], 0.f);
    }
    __syncthreads();

    // out = h + h1 @ w2 + b2   (w2 k-major [512][256]) -> s_upd (reuse)
    {
        int c = t & 255, rg = t >> 8;
        float acc[4];
#pragma unroll
        for (int i = 0; i < 4; i++) acc[i] = b2[c];
        for (int k = 0; k < 512; k += 4) {
            float w0 = w2[(k + 0) * 256 + c];
            float w1v = w2[(k + 1) * 256 + c];
            float w2v = w2[(k + 2) * 256 + c];
            float w3 = w2[(k + 3) * 256 + c];
#pragma unroll
            for (int i = 0; i < 4; i++) {
                const float4 a = *(const float4*)(s_h1 + (rg * 4 + i) * 512 + k);
                acc[i] += a.x * w0 + a.y * w1v + a.z * w2v + a.w * w3;
            }
        }
#pragma unroll
        for (int i = 0; i < 4; i++) {
            int r = rg * 4 + i;
            float o = acc[i] + s_h[r * 256 + c];
            s_upd[r * 256 + c] = o;
            if (last) dout[(b * 8 + r) * 256 + c] = o;
        }
    }
    __syncthreads();

    if (!last) {
        // next iteration: sln = LN(slots), q = sln @ Wq, zero accumulators
        row_ln8(s_upd, s_sln, s_red, t);
        q_and_store(s_sln, Wq, b, t);
    }
}

// =====================================================================
extern "C" void kernel_launch(void* const* d_in, const int* in_sizes, int n_in,
                              void* d_out, int out_size) {
    (void)in_sizes; (void)n_in; (void)out_size;
    const float* inputs = (const float*)d_in[0];
    const float* noise  = (const float*)d_in[1];
    const float* Wk     = (const float*)d_in[2];
    const float* Wv     = (const float*)d_in[3];
    const float* Wq     = (const float*)d_in[4];
    const float* mu     = (const float*)d_in[5];
    const float* ls     = (const float*)d_in[6];
    const float* wih    = (const float*)d_in[7];
    const float* whh    = (const float*)d_in[8];
    const float* bih    = (const float*)d_in[9];
    const float* bhh    = (const float*)d_in[10];
    const float* w1     = (const float*)d_in[11];
    const float* b1     = (const float*)d_in[12];
    const float* w2     = (const float*)d_in[13];
    const float* b2     = (const float*)d_in[14];

    cudaFuncSetAttribute(proj_mma_kernel,
                         cudaFuncAttributeMaxDynamicSharedMemorySize, 6 * STG);
    cudaFuncSetAttribute(slot_tail_kernel,
                         cudaFuncAttributeMaxDynamicSharedMemorySize, TAIL_SMEM);

    ln_stats_kernel<<<ROWSv / 8, 256>>>(inputs);
    wsum_kernel<<<8, 256>>>(Wk, Wv);
    transpose_w_kernel<<<dim3(16, 16), dim3(32, 8)>>>(Wk, Wv);
    transpose_gru_kernel<<<dim3(24, 8, 2), dim3(32, 8)>>>(wih, whh);
    proj_mma_kernel<<<dim3(4, 1024), 256, 6 * STG>>>();
    slot_init_kernel<<<32, 512>>>(noise, mu, ls, Wq);

    for (int it = 0; it < 3; it++) {
        attn_upd_kernel<<<dim3(32, 32), 256>>>();
        slot_tail_kernel<<<32, 512, TAIL_SMEM>>>(bih, bhh, w1, b1, w2, b2, Wq,
                                                 (float*)d_out, it == 2);
    }
}

// round 15
// speedup vs baseline: 1.0119x; 1.0119x over previous
#include <cuda_runtime.h>
#include <cuda_bf16.h>
#include <math.h>
#include <stdint.h>

// Problem constants
#define Bv    32
#define Nv    4096
#define INPv  512
#define ROWSv (Bv*Nv)   // 131072

// ---------------- scratch (static device globals; no allocs allowed) ----------------
__device__ __align__(16) float g_k[16777216];      // bf16 image [ROWS][256]
__device__ __align__(16) float g_v[16777216];      // bf16 image [ROWS][256]
__device__ __align__(16) uint16_t g_xh[67108864];  // bf16 image of X, MMA-swizzled [row][1024B]
__device__ __align__(16) uint16_t g_wth[262144];   // bf16 image of fused W^T [n][1024B]
__device__ __align__(16) float g_stats[262144];    // [ROWS][2] mean,rstd
__device__ __align__(16) float g_wsum[512];        // colsum of [Wk|Wv]
__device__ __align__(16) float g_wihT[196608];     // k-major wih^T [256][768]
__device__ __align__(16) float g_whhT[196608];     // k-major whh^T [256][768]
__device__ __align__(16) float g_sln[65536];
__device__ __align__(16) float g_q[65536];
__device__ __align__(16) float g_upd[65536];
__device__ __align__(16) float g_colsum[256];

__device__ __forceinline__ uint32_t smem_u32(const void* p) {
    uint32_t a;
    asm("{ .reg .u64 t; cvta.to.shared.u64 t, %1; cvt.u32.u64 %0, t; }" : "=r"(a) : "l"(p));
    return a;
}
__device__ __forceinline__ void cpasync16(uint32_t d, const void* g) {
    asm volatile("cp.async.cg.shared.global [%0], [%1], 16;" :: "r"(d), "l"(g));
}
#define CP_COMMIT() asm volatile("cp.async.commit_group;" ::: "memory")
#define CP_WAIT0()  asm volatile("cp.async.wait_group 0;" ::: "memory")

// image byte offset within a row for element k (k-pair permute + region rotation by row)
__device__ __forceinline__ int img_off(int k, int row) {
    int bblk = k >> 6;
    int c    = (k >> 4) & 3;
    int kk   = k & 15;
    int p    = kk >> 1;
    int slot = ((p & 3) << 1) | (p >> 2);
    int reg  = (c + row) & 3;
    return bblk * 128 + reg * 32 + slot * 4 + (kk & 1) * 2;
}

// ---------------- LN stats + bf16 swizzled image of X ----------------
__global__ void ln_stats_kernel(const float* __restrict__ X) {
    __shared__ __align__(16) uint16_t img[8][512];
    int warp = threadIdx.x >> 5, lane = threadIdx.x & 31;
    int row  = blockIdx.x * 8 + warp;
    const float* xr = X + (size_t)row * INPv;
    float4 v[4];
    float s = 0.f, s2 = 0.f;
#pragma unroll
    for (int j = 0; j < 4; j++) {
        v[j] = *(const float4*)(xr + lane * 4 + 128 * j);
        s  += v[j].x + v[j].y + v[j].z + v[j].w;
        s2 += v[j].x * v[j].x + v[j].y * v[j].y + v[j].z * v[j].z + v[j].w * v[j].w;
    }
#pragma unroll
    for (int off = 16; off; off >>= 1) {
        s  += __shfl_down_sync(0xffffffffu, s,  off);
        s2 += __shfl_down_sync(0xffffffffu, s2, off);
    }
    if (!lane) {
        float m   = s * (1.f / INPv);
        float var = s2 * (1.f / INPv) - m * m;
        g_stats[row * 2]     = m;
        g_stats[row * 2 + 1] = rsqrtf(var + 1e-5f);
    }
#pragma unroll
    for (int j = 0; j < 4; j++) {
        int k0 = lane * 4 + 128 * j;
        float vals[4] = {v[j].x, v[j].y, v[j].z, v[j].w};
#pragma unroll
        for (int t = 0; t < 2; t++) {
            int k = k0 + 2 * t;
            __nv_bfloat162 h2 = __floats2bfloat162_rn(vals[2 * t], vals[2 * t + 1]);
            *(uint32_t*)((char*)img[warp] + img_off(k, row)) = *(uint32_t*)&h2;
        }
    }
    __syncwarp();
    uint4* srcp = (uint4*)img[warp];
    uint4* dstp = (uint4*)(g_xh + (size_t)row * 512);
    dstp[lane]      = srcp[lane];
    dstp[lane + 32] = srcp[lane + 32];
}

// ---------------- column sums of Wk|Wv ----------------
__global__ void wsum_kernel(const float* __restrict__ Wk, const float* __restrict__ Wv) {
    __shared__ float red[4][64];
    int b = blockIdx.x;
    int c0 = b * 64;
    int col = threadIdx.x & 63, part = threadIdx.x >> 6;
    const float* W = (c0 < 256) ? Wk : Wv;
    int cc = (c0 & 255) + col;
    float s = 0.f;
    for (int k = part * 128; k < part * 128 + 128; k++) s += W[k * 256 + cc];
    red[part][col] = s;
    __syncthreads();
    if (threadIdx.x < 64) {
        g_wsum[c0 + threadIdx.x] = red[0][threadIdx.x] + red[1][threadIdx.x]
                                 + red[2][threadIdx.x] + red[3][threadIdx.x];
    }
}

// ---------------- transposed fused-W bf16 image: g_wth[n][k-image] ----------------
__global__ void transpose_w_kernel(const float* __restrict__ Wk, const float* __restrict__ Wv) {
    __shared__ float t[32][33];
    int n0 = blockIdx.x * 32, k0 = blockIdx.y * 32;
    int tx = threadIdx.x, ty = threadIdx.y;     // (32, 8)
    const float* W = (n0 < 256) ? Wk : Wv;
    int col0 = n0 & 255;
#pragma unroll
    for (int j = 0; j < 4; j++) {
        int k = k0 + ty + 8 * j;
        t[ty + 8 * j][tx] = W[(size_t)k * 256 + col0 + tx];
    }
    __syncthreads();
#pragma unroll
    for (int j = 0; j < 4; j++) {
        int n = n0 + ty + 8 * j;
        int k = k0 + tx;
        __nv_bfloat16 h = __float2bfloat16(t[tx][ty + 8 * j]);
        g_wth[(size_t)n * 512 + (img_off(k, n) >> 1)] = *(uint16_t*)&h;
    }
}

// ---------------- transpose GRU weights to k-major [256][768] ----------------
__global__ void transpose_gru_kernel(const float* __restrict__ wih, const float* __restrict__ whh) {
    __shared__ float t[32][33];
    const float* src = blockIdx.z ? whh : wih;
    float* dst = blockIdx.z ? g_whhT : g_wihT;
    int r0 = blockIdx.x * 32, k0 = blockIdx.y * 32;
    int tx = threadIdx.x, ty = threadIdx.y;
#pragma unroll
    for (int j = 0; j < 4; j++)
        t[ty + 8 * j][tx] = src[(size_t)(r0 + ty + 8 * j) * 256 + k0 + tx];
    __syncthreads();
#pragma unroll
    for (int j = 0; j < 4; j++)
        dst[(size_t)(k0 + ty + 8 * j) * 768 + r0 + tx] = t[tx][ty + 8 * j];
}

// ---------------- bf16 mma.sync projection, double-buffered (round-11 proven) ----------------
#define STG 16384   // 128 rows x 128 B per stage tile

__global__ __launch_bounds__(256, 2)
void proj_mma_kernel() {
    extern __shared__ char dsm[];
    uint32_t sb = smem_u32(dsm);
    int n0   = blockIdx.x * 128;
    int row0 = blockIdx.y * 128;
    int tid  = threadIdx.x;
    int wid  = tid >> 5, lane = tid & 31;
    int warp_m = wid >> 2, warp_n = wid & 3;
    int mb = warp_m * 64, nb = warp_n * 32;
    int grp = lane >> 2, q = lane & 3;
    int lr = tid >> 1, lh = tid & 1;

    float acc[4][4][4];
#pragma unroll
    for (int f = 0; f < 4; f++)
#pragma unroll
        for (int g = 0; g < 4; g++)
#pragma unroll
            for (int c = 0; c < 4; c++) acc[f][g][c] = 0.f;

    auto issue = [&](int s, int buf) {
        const char* srcA = (const char*)g_xh  + (size_t)(row0 + lr) * 1024 + s * 128 + lh * 64;
        const char* srcB = (const char*)g_wth + (size_t)(n0   + lr) * 1024 + s * 128 + lh * 64;
        uint32_t dA = sb + buf * STG       + lr * 128 + lh * 64;
        uint32_t dB = sb + (2 + buf) * STG + lr * 128 + lh * 64;
#pragma unroll
        for (int gi = 0; gi < 4; gi++) {
            cpasync16(dA + gi * 16, srcA + gi * 16);
            cpasync16(dB + gi * 16, srcB + gi * 16);
        }
    };

    issue(0, 0);
    CP_COMMIT();

    int buf = 0;
    for (int s = 0; s < 8; s++) {
        CP_WAIT0();
        __syncthreads();
        if (s < 7) { issue(s + 1, buf ^ 1); CP_COMMIT(); }

        const char* As = dsm + buf * STG;
        const char* Bs = dsm + (2 + buf) * STG;
#pragma unroll
        for (int c = 0; c < 4; c++) {
            uint2 bfr[4];
#pragma unroll
            for (int g = 0; g < 4; g++) {
                int rn = nb + g * 8 + grp;
                bfr[g] = *(const uint2*)(Bs + rn * 128 + ((c + rn) & 3) * 32 + q * 8);
            }
#pragma unroll
            for (int f = 0; f < 4; f++) {
                int r0 = mb + f * 16 + grp;
                int r1 = r0 + 8;
                uint2 aa = *(const uint2*)(As + r0 * 128 + ((c + r0) & 3) * 32 + q * 8);
                uint2 ab = *(const uint2*)(As + r1 * 128 + ((c + r1) & 3) * 32 + q * 8);
#pragma unroll
                for (int g = 0; g < 4; g++) {
                    asm volatile(
                        "mma.sync.aligned.m16n8k16.row.col.f32.bf16.bf16.f32 "
                        "{%0,%1,%2,%3}, {%4,%5,%6,%7}, {%8,%9}, {%0,%1,%2,%3};"
                        : "+f"(acc[f][g][0]), "+f"(acc[f][g][1]),
                          "+f"(acc[f][g][2]), "+f"(acc[f][g][3])
                        : "r"(aa.x), "r"(ab.x), "r"(aa.y), "r"(ab.y),
                          "r"(bfr[g].x), "r"(bfr[g].y));
                }
            }
        }
        buf ^= 1;
    }

    __nv_bfloat16* kh = (__nv_bfloat16*)g_k;
    __nv_bfloat16* vh = (__nv_bfloat16*)g_v;
#pragma unroll
    for (int f = 0; f < 4; f++) {
        int r0g = row0 + mb + f * 16 + grp;
        int r1g = r0g + 8;
        float m0 = g_stats[r0g * 2], s0 = g_stats[r0g * 2 + 1];
        float m1 = g_stats[r1g * 2], s1 = g_stats[r1g * 2 + 1];
        float mr0 = m0 * s0, mr1 = m1 * s1;
#pragma unroll
        for (int g = 0; g < 4; g++) {
            int nglob = n0 + nb + g * 8 + q * 2;
            float ws0 = g_wsum[nglob], ws1 = g_wsum[nglob + 1];
            __nv_bfloat162 o0 = __floats2bfloat162_rn(
                s0 * acc[f][g][0] - mr0 * ws0, s0 * acc[f][g][1] - mr0 * ws1);
            __nv_bfloat162 o1 = __floats2bfloat162_rn(
                s1 * acc[f][g][2] - mr1 * ws0, s1 * acc[f][g][3] - mr1 * ws1);
            if (nglob < 256) {
                *(__nv_bfloat162*)(kh + (size_t)r0g * 256 + nglob) = o0;
                *(__nv_bfloat162*)(kh + (size_t)r1g * 256 + nglob) = o1;
            } else {
                *(__nv_bfloat162*)(vh + (size_t)r0g * 256 + nglob - 256) = o0;
                *(__nv_bfloat162*)(vh + (size_t)r1g * 256 + nglob - 256) = o1;
            }
        }
    }
}

// ---------------- row LN over 8 rows x 256 (512 threads), src/dst in smem ----------------
__device__ __forceinline__ void row_ln8(const float* src, float* dst, float* s_red, int t) {
    int r = t >> 6, l64 = t & 63;
    float s = 0.f, s2 = 0.f;
#pragma unroll
    for (int j = 0; j < 4; j++) {
        float v = src[r * 256 + l64 + 64 * j];
        s += v; s2 += v * v;
    }
#pragma unroll
    for (int off = 16; off; off >>= 1) {
        s  += __shfl_down_sync(0xffffffffu, s,  off);
        s2 += __shfl_down_sync(0xffffffffu, s2, off);
    }
    int w = t >> 5;
    if ((t & 31) == 0) { s_red[w * 2] = s; s_red[w * 2 + 1] = s2; }
    __syncthreads();
    if (t < 8) {
        float ts = s_red[4 * t]     + s_red[4 * t + 2];
        float t2 = s_red[4 * t + 1] + s_red[4 * t + 3];
        float m = ts * (1.f / 256.f), var = t2 * (1.f / 256.f) - m * m;
        s_red[32 + 2 * t]     = m;
        s_red[32 + 2 * t + 1] = rsqrtf(var + 1e-5f);
    }
    __syncthreads();
    for (int i = t; i < 2048; i += 512) {
        int rr = i >> 8;
        dst[i] = (src[i] - s_red[32 + 2 * rr]) * s_red[33 + 2 * rr];
    }
    __syncthreads();
}

// q = sln @ Wq, sln in smem; also store sln to global; zero accumulators
__device__ __forceinline__ void q_and_store(const float* s_sln, const float* __restrict__ Wq,
                                            int b, int t) {
    for (int i = t; i < 2048; i += 512) g_sln[b * 2048 + i] = s_sln[i];
    int c = t & 255, rg = t >> 8;
    float acc[4] = {0.f, 0.f, 0.f, 0.f};
    for (int k = 0; k < 256; k += 4) {
        float w0 = Wq[(k + 0) * 256 + c];
        float w1v = Wq[(k + 1) * 256 + c];
        float w2v = Wq[(k + 2) * 256 + c];
        float w3 = Wq[(k + 3) * 256 + c];
#pragma unroll
        for (int i = 0; i < 4; i++) {
            const float4 a = *(const float4*)(s_sln + (rg * 4 + i) * 256 + k);
            acc[i] += a.x * w0 + a.y * w1v + a.z * w2v + a.w * w3;
        }
    }
#pragma unroll
    for (int i = 0; i < 4; i++)
        g_q[b * 2048 + (rg * 4 + i) * 256 + c] = acc[i];
    for (int i = t; i < 2048; i += 512) g_upd[b * 2048 + i] = 0.f;
    if (t < 8) g_colsum[b * 8 + t] = 0.f;
}

// ---------------- prologue: slots init + LN + q ----------------
__global__ __launch_bounds__(512)
void slot_init_kernel(const float* __restrict__ noise, const float* __restrict__ mu,
                      const float* __restrict__ ls, const float* __restrict__ Wq) {
    __shared__ float s_h[2048];
    __shared__ float s_sln[2048];
    __shared__ float s_red[64];
    int b = blockIdx.x, t = threadIdx.x;
    for (int i = t; i < 2048; i += 512) {
        int d = i & 255;
        s_h[i] = mu[d] + __expf(ls[d]) * noise[b * 2048 + i];
    }
    __syncthreads();
    row_ln8(s_h, s_sln, s_red, t);
    q_and_store(s_sln, Wq, b, t);
}

// ---------------- fused attention + updates (bf16 k/v) ----------------
__global__ __launch_bounds__(256)
void attn_upd_kernel() {
    __shared__ __align__(16) float qs[2048];
    __shared__ float ps[128 * 8];
    int b  = blockIdx.y;
    int n0 = blockIdx.x * 128;
    int tid = threadIdx.x;
    int warp = tid >> 5, lane = tid & 31;
    const __nv_bfloat16* kh = (const __nv_bfloat16*)g_k;
    const __nv_bfloat16* vh = (const __nv_bfloat16*)g_v;

    for (int i = tid; i < 2048; i += 256) qs[i] = g_q[(size_t)b * 2048 + i];
    __syncthreads();

    const float scale = 0.0625f;
    float csum[8] = {};
#pragma unroll
    for (int g = 0; g < 4; g++) {
        int nb = warp * 16 + g * 4;
        const uint32_t* kp = (const uint32_t*)(kh + ((size_t)(b * Nv + n0 + nb)) * 256);
        float part[4][8] = {};
#pragma unroll
        for (int j = 0; j < 4; j++) {
            int pi = lane + 32 * j;
            float2 kv[4];
#pragma unroll
            for (int i = 0; i < 4; i++)
                kv[i] = __bfloat1622float2(*(const __nv_bfloat162*)&kp[i * 128 + pi]);
#pragma unroll
            for (int s = 0; s < 8; s++) {
                float2 qv = *(const float2*)(qs + s * 256 + 2 * pi);
#pragma unroll
                for (int i = 0; i < 4; i++)
                    part[i][s] += kv[i].x * qv.x + kv[i].y * qv.y;
            }
        }
#pragma unroll
        for (int i = 0; i < 4; i++)
#pragma unroll
            for (int s = 0; s < 8; s++)
#pragma unroll
                for (int off = 16; off; off >>= 1)
                    part[i][s] += __shfl_down_sync(0xffffffffu, part[i][s], off);
        if (lane == 0) {
#pragma unroll
            for (int i = 0; i < 4; i++) {
                float m = -1e30f;
#pragma unroll
                for (int s = 0; s < 8; s++) m = fmaxf(m, part[i][s] * scale);
                float e[8], sum = 0.f;
#pragma unroll
                for (int s = 0; s < 8; s++) { e[s] = __expf(part[i][s] * scale - m); sum += e[s]; }
                float inv = 1.f / sum;
                int nl = warp * 16 + g * 4 + i;
#pragma unroll
                for (int s = 0; s < 8; s++) {
                    float p = e[s] * inv + 1e-8f;
                    ps[nl * 8 + s] = p;
                    csum[s] += p;
                }
            }
        }
    }
    if (lane == 0) {
#pragma unroll
        for (int s = 0; s < 8; s++) atomicAdd(&g_colsum[b * 8 + s], csum[s]);
    }
    __syncthreads();

    int d = tid;
    float acc[8] = {};
    const __nv_bfloat16* vb = vh + ((size_t)(b * Nv + n0)) * 256;
#pragma unroll 4
    for (int n = 0; n < 128; n++) {
        float vv = __bfloat162float(vb[(size_t)n * 256 + d]);
#pragma unroll
        for (int s = 0; s < 8; s++) acc[s] += ps[n * 8 + s] * vv;
    }
#pragma unroll
    for (int s = 0; s < 8; s++) atomicAdd(&g_upd[(b * 8 + s) * 256 + d], acc[s]);
}

// ---------------- fused slot tail: GRU gemms + combine + LN + MLP + next LN/q ----------------
#define TAIL_SMEM (24640 * 4)

__global__ __launch_bounds__(512, 1)
void slot_tail_kernel(const float* __restrict__ bih, const float* __restrict__ bhh,
                      const float* __restrict__ w1, const float* __restrict__ b1,
                      const float* __restrict__ w2, const float* __restrict__ b2,
                      const float* __restrict__ Wq, float* __restrict__ dout, int last) {
    extern __shared__ float sm[];
    float* s_upd = sm;            // 2048
    float* s_sln = sm + 2048;     // 2048
    float* s_gx  = sm + 4096;     // 6144
    float* s_gh  = sm + 10240;    // 6144
    float* s_h   = sm + 16384;    // 2048
    float* s_y   = sm + 18432;    // 2048
    float* s_h1  = sm + 20480;    // 4096
    float* s_red = sm + 24576;    // 64
    int b = blockIdx.x, t = threadIdx.x;

    for (int i = t; i < 2048; i += 512) {
        int r = i >> 8;
        s_upd[i] = g_upd[b * 2048 + i] / g_colsum[b * 8 + r];
        s_sln[i] = g_sln[b * 2048 + i];
    }
    __syncthreads();

#pragma unroll
    for (int jj = 0; jj < 3; jj++) {
        int job = t + 512 * jj;
        int isx = (job < 768);
        int c = isx ? job : job - 768;
        const float* WT = isx ? g_wihT : g_whhT;
        const float* A  = isx ? s_upd : s_sln;
        float bias = isx ? bih[c] : bhh[c];
        float acc[8];
#pragma unroll
        for (int r = 0; r < 8; r++) acc[r] = bias;
        for (int k = 0; k < 256; k += 4) {
            float w0 = WT[(k + 0) * 768 + c];
            float w1v = WT[(k + 1) * 768 + c];
            float w2v = WT[(k + 2) * 768 + c];
            float w3 = WT[(k + 3) * 768 + c];
#pragma unroll
            for (int r = 0; r < 8; r++) {
                const float4 a = *(const float4*)(A + r * 256 + k);
                acc[r] += a.x * w0 + a.y * w1v + a.z * w2v + a.w * w3;
            }
        }
        float* dst = isx ? s_gx : s_gh;
#pragma unroll
        for (int r = 0; r < 8; r++) dst[r * 768 + c] = acc[r];
    }
    __syncthreads();

    for (int i = t; i < 2048; i += 512) {
        int r = i >> 8, d = i & 255;
        float xr = s_gx[r * 768 + d],       hr = s_gh[r * 768 + d];
        float xz = s_gx[r * 768 + 256 + d], hz = s_gh[r * 768 + 256 + d];
        float xn = s_gx[r * 768 + 512 + d], hn = s_gh[r * 768 + 512 + d];
        float rg = 1.f / (1.f + __expf(-(xr + hr)));
        float zg = 1.f / (1.f + __expf(-(xz + hz)));
        float ng = tanhf(xn + rg * hn);
        s_h[i] = (1.f - zg) * ng + zg * s_sln[i];
    }
    __syncthreads();

    row_ln8(s_h, s_y, s_red, t);

    {
        int c = t;
        float acc[8];
#pragma unroll
        for (int r = 0; r < 8; r++) acc[r] = b1[c];
        for (int k = 0; k < 256; k += 4) {
            float w0 = w1[(k + 0) * 512 + c];
            float w1v = w1[(k + 1) * 512 + c];
            float w2v = w1[(k + 2) * 512 + c];
            float w3 = w1[(k + 3) * 512 + c];
#pragma unroll
            for (int r = 0; r < 8; r++) {
                const float4 a = *(const float4*)(s_y + r * 256 + k);
                acc[r] += a.x * w0 + a.y * w1v + a.z * w2v + a.w * w3;
            }
        }
#pragma unroll
        for (int r = 0; r < 8; r++) s_h1[r * 512 + c] = fmaxf(acc[r], 0.f);
    }
    __syncthreads();

    {
        int c = t & 255, rg = t >> 8;
        float acc[4];
#pragma unroll
        for (int i = 0; i < 4; i++) acc[i] = b2[c];
        for (int k = 0; k < 512; k += 4) {
            float w0 = w2[(k + 0) * 256 + c];
            float w1v = w2[(k + 1) * 256 + c];
            float w2v = w2[(k + 2) * 256 + c];
            float w3 = w2[(k + 3) * 256 + c];
#pragma unroll
            for (int i = 0; i < 4; i++) {
                const float4 a = *(const float4*)(s_h1 + (rg * 4 + i) * 512 + k);
                acc[i] += a.x * w0 + a.y * w1v + a.z * w2v + a.w * w3;
            }
        }
#pragma unroll
        for (int i = 0; i < 4; i++) {
            int r = rg * 4 + i;
            float o = acc[i] + s_h[r * 256 + c];
            s_upd[r * 256 + c] = o;
            if (last) dout[(b * 8 + r) * 256 + c] = o;
        }
    }
    __syncthreads();

    if (!last) {
        row_ln8(s_upd, s_sln, s_red, t);
        q_and_store(s_sln, Wq, b, t);
    }
}

// =====================================================================
extern "C" void kernel_launch(void* const* d_in, const int* in_sizes, int n_in,
                              void* d_out, int out_size) {
    (void)in_sizes; (void)n_in; (void)out_size;
    const float* inputs = (const float*)d_in[0];
    const float* noise  = (const float*)d_in[1];
    const float* Wk     = (const float*)d_in[2];
    const float* Wv     = (const float*)d_in[3];
    const float* Wq     = (const float*)d_in[4];
    const float* mu     = (const float*)d_in[5];
    const float* ls     = (const float*)d_in[6];
    const float* wih    = (const float*)d_in[7];
    const float* whh    = (const float*)d_in[8];
    const float* bih    = (const float*)d_in[9];
    const float* bhh    = (const float*)d_in[10];
    const float* w1     = (const float*)d_in[11];
    const float* b1     = (const float*)d_in[12];
    const float* w2     = (const float*)d_in[13];
    const float* b2     = (const float*)d_in[14];

    cudaFuncSetAttribute(proj_mma_kernel,
                         cudaFuncAttributeMaxDynamicSharedMemorySize, 4 * STG);
    cudaFuncSetAttribute(slot_tail_kernel,
                         cudaFuncAttributeMaxDynamicSharedMemorySize, TAIL_SMEM);

    // proj kept as launch #4 so the ncu capture slot profiles it
    ln_stats_kernel<<<ROWSv / 8, 256>>>(inputs);
    wsum_kernel<<<8, 256>>>(Wk, Wv);
    transpose_w_kernel<<<dim3(16, 16), dim3(32, 8)>>>(Wk, Wv);
    proj_mma_kernel<<<dim3(4, 1024), 256, 4 * STG>>>();
    transpose_gru_kernel<<<dim3(24, 8, 2), dim3(32, 8)>>>(wih, whh);
    slot_init_kernel<<<32, 512>>>(noise, mu, ls, Wq);

    for (int it = 0; it < 3; it++) {
        attn_upd_kernel<<<dim3(32, 32), 256>>>();
        slot_tail_kernel<<<32, 512, TAIL_SMEM>>>(bih, bhh, w1, b1, w2, b2, Wq,
                                                 (float*)d_out, it == 2);
    }
}

// round 16
// speedup vs baseline: 1.1837x; 1.1697x over previous
#include <cuda_runtime.h>
#include <cuda_bf16.h>
#include <math.h>
#include <stdint.h>

// Problem constants
#define Bv    32
#define Nv    4096
#define INPv  512
#define ROWSv (Bv*Nv)   // 131072

// ---------------- scratch (static device globals; no allocs allowed) ----------------
__device__ __align__(16) float g_k[16777216];      // bf16 image [ROWS][256]
__device__ __align__(16) float g_v[16777216];      // bf16 image [ROWS][256]
__device__ __align__(16) uint16_t g_xh[67108864];  // bf16 image of X, MMA-swizzled [row][1024B]
__device__ __align__(16) uint16_t g_wth[262144];   // bf16 image of fused W^T [n][1024B]
__device__ __align__(16) float g_stats[262144];    // [ROWS][2] mean,rstd
__device__ __align__(16) float g_wsum[512];        // colsum of [Wk|Wv]
__device__ __align__(16) float g_slots[65536];
__device__ __align__(16) float g_sln[65536];
__device__ __align__(16) float g_q[65536];
__device__ __align__(16) float g_upd[65536];
__device__ __align__(16) float g_colsum[256];
__device__ __align__(16) float g_gx[196608];       // [256][768]
__device__ __align__(16) float g_gh[196608];
__device__ __align__(16) float g_h1[131072];       // [256][512]
__device__ __align__(16) float g_y[65536];

__device__ __forceinline__ uint32_t smem_u32(const void* p) {
    uint32_t a;
    asm("{ .reg .u64 t; cvta.to.shared.u64 t, %1; cvt.u32.u64 %0, t; }" : "=r"(a) : "l"(p));
    return a;
}
__device__ __forceinline__ void cpasync16(uint32_t d, const void* g) {
    asm volatile("cp.async.cg.shared.global [%0], [%1], 16;" :: "r"(d), "l"(g));
}
#define CP_COMMIT() asm volatile("cp.async.commit_group;" ::: "memory")
#define CP_WAIT0()  asm volatile("cp.async.wait_group 0;" ::: "memory")

// image byte offset within a row for element k (k-pair permute + region rotation by row)
__device__ __forceinline__ int img_off(int k, int row) {
    int bblk = k >> 6;
    int c    = (k >> 4) & 3;
    int kk   = k & 15;
    int p    = kk >> 1;
    int slot = ((p & 3) << 1) | (p >> 2);
    int reg  = (c + row) & 3;
    return bblk * 128 + reg * 32 + slot * 4 + (kk & 1) * 2;
}

// ---------------- row LN over 8 rows x 256 (512 threads), src/dst in smem ----------------
__device__ __forceinline__ void row_ln8(const float* src, float* dst, float* s_red, int t) {
    int r = t >> 6, l64 = t & 63;
    float s = 0.f, s2 = 0.f;
#pragma unroll
    for (int j = 0; j < 4; j++) {
        float v = src[r * 256 + l64 + 64 * j];
        s += v; s2 += v * v;
    }
#pragma unroll
    for (int off = 16; off; off >>= 1) {
        s  += __shfl_down_sync(0xffffffffu, s,  off);
        s2 += __shfl_down_sync(0xffffffffu, s2, off);
    }
    int w = t >> 5;
    if ((t & 31) == 0) { s_red[w * 2] = s; s_red[w * 2 + 1] = s2; }
    __syncthreads();
    if (t < 8) {
        float ts = s_red[4 * t]     + s_red[4 * t + 2];
        float t2 = s_red[4 * t + 1] + s_red[4 * t + 3];
        float m = ts * (1.f / 256.f), var = t2 * (1.f / 256.f) - m * m;
        s_red[32 + 2 * t]     = m;
        s_red[32 + 2 * t + 1] = rsqrtf(var + 1e-5f);
    }
    __syncthreads();
    for (int i = t; i < 2048; i += 512) {
        int rr = i >> 8;
        dst[i] = (src[i] - s_red[32 + 2 * rr]) * s_red[33 + 2 * rr];
    }
    __syncthreads();
}

// q = sln @ Wq, sln in smem; store sln; zero accumulators (512 threads)
__device__ __forceinline__ void q_and_store(const float* s_sln, const float* __restrict__ Wq,
                                            int b, int t) {
    for (int i = t; i < 2048; i += 512) g_sln[b * 2048 + i] = s_sln[i];
    int c = t & 255, rg = t >> 8;
    float acc[4] = {0.f, 0.f, 0.f, 0.f};
    for (int k = 0; k < 256; k += 4) {
        float w0 = Wq[(k + 0) * 256 + c];
        float w1v = Wq[(k + 1) * 256 + c];
        float w2v = Wq[(k + 2) * 256 + c];
        float w3 = Wq[(k + 3) * 256 + c];
#pragma unroll
        for (int i = 0; i < 4; i++) {
            const float4 a = *(const float4*)(s_sln + (rg * 4 + i) * 256 + k);
            acc[i] += a.x * w0 + a.y * w1v + a.z * w2v + a.w * w3;
        }
    }
#pragma unroll
    for (int i = 0; i < 4; i++)
        g_q[b * 2048 + (rg * 4 + i) * 256 + c] = acc[i];
    for (int i = t; i < 2048; i += 512) g_upd[b * 2048 + i] = 0.f;
    if (t < 8) g_colsum[b * 8 + t] = 0.f;
}

// ---------------- prep: W transpose->bf16 image, wsum, slots init+LN+q (one launch) ----------------
__global__ __launch_bounds__(512)
void prep_kernel(const float* __restrict__ Wk, const float* __restrict__ Wv,
                 const float* __restrict__ noise, const float* __restrict__ mu,
                 const float* __restrict__ ls, const float* __restrict__ Wq) {
    __shared__ __align__(16) float sbuf[4160];
    int blk = blockIdx.x, t = threadIdx.x;
    if (blk < 256) {
        // transpose fused W tile -> g_wth bf16 image
        float* tt = sbuf;                 // [32][33]
        int n0 = (blk >> 4) * 32, k0 = (blk & 15) * 32;
        const float* W = (n0 < 256) ? Wk : Wv;
        int col0 = n0 & 255;
        int tx = t & 31, ty = t >> 5;     // ty 0..15
#pragma unroll
        for (int j = 0; j < 2; j++) {
            int k = k0 + ty + 16 * j;
            tt[(ty + 16 * j) * 33 + tx] = W[(size_t)k * 256 + col0 + tx];
        }
        __syncthreads();
#pragma unroll
        for (int j = 0; j < 2; j++) {
            int n = n0 + ty + 16 * j;
            int k = k0 + tx;
            __nv_bfloat16 h = __float2bfloat16(tt[tx * 33 + ty + 16 * j]);
            g_wth[(size_t)n * 512 + (img_off(k, n) >> 1)] = *(uint16_t*)&h;
        }
    } else if (blk < 264) {
        // column sums of [Wk|Wv]
        int c0 = (blk - 256) * 64;
        int col = t & 63, part = t >> 6;  // 8 parts x 64 k
        const float* W = (c0 < 256) ? Wk : Wv;
        int cc = (c0 & 255) + col;
        float s = 0.f;
        for (int k = part * 64; k < part * 64 + 64; k++) s += W[k * 256 + cc];
        sbuf[part * 64 + col] = s;
        __syncthreads();
        if (t < 64) {
            float acc = 0.f;
#pragma unroll
            for (int p = 0; p < 8; p++) acc += sbuf[p * 64 + t];
            g_wsum[c0 + t] = acc;
        }
    } else {
        // slots init + LN + q + zero accumulators (iteration 1)
        float* s_h   = sbuf;
        float* s_sln = sbuf + 2048;
        float* s_red = sbuf + 4096;
        int b = blk - 264;
        for (int i = t; i < 2048; i += 512) {
            int d = i & 255;
            s_h[i] = mu[d] + __expf(ls[d]) * noise[b * 2048 + i];
        }
        __syncthreads();
        row_ln8(s_h, s_sln, s_red, t);
        q_and_store(s_sln, Wq, b, t);
    }
}

// ---------------- LN stats + bf16 swizzled image of X ----------------
__global__ void ln_stats_kernel(const float* __restrict__ X) {
    __shared__ __align__(16) uint16_t img[8][512];
    int warp = threadIdx.x >> 5, lane = threadIdx.x & 31;
    int row  = blockIdx.x * 8 + warp;
    const float* xr = X + (size_t)row * INPv;
    float4 v[4];
    float s = 0.f, s2 = 0.f;
#pragma unroll
    for (int j = 0; j < 4; j++) {
        v[j] = *(const float4*)(xr + lane * 4 + 128 * j);
        s  += v[j].x + v[j].y + v[j].z + v[j].w;
        s2 += v[j].x * v[j].x + v[j].y * v[j].y + v[j].z * v[j].z + v[j].w * v[j].w;
    }
#pragma unroll
    for (int off = 16; off; off >>= 1) {
        s  += __shfl_down_sync(0xffffffffu, s,  off);
        s2 += __shfl_down_sync(0xffffffffu, s2, off);
    }
    if (!lane) {
        float m   = s * (1.f / INPv);
        float var = s2 * (1.f / INPv) - m * m;
        g_stats[row * 2]     = m;
        g_stats[row * 2 + 1] = rsqrtf(var + 1e-5f);
    }
#pragma unroll
    for (int j = 0; j < 4; j++) {
        int k0 = lane * 4 + 128 * j;
        float vals[4] = {v[j].x, v[j].y, v[j].z, v[j].w};
#pragma unroll
        for (int t = 0; t < 2; t++) {
            int k = k0 + 2 * t;
            __nv_bfloat162 h2 = __floats2bfloat162_rn(vals[2 * t], vals[2 * t + 1]);
            *(uint32_t*)((char*)img[warp] + img_off(k, row)) = *(uint32_t*)&h2;
        }
    }
    __syncwarp();
    uint4* srcp = (uint4*)img[warp];
    uint4* dstp = (uint4*)(g_xh + (size_t)row * 512);
    dstp[lane]      = srcp[lane];
    dstp[lane + 32] = srcp[lane + 32];
}

// ---------------- bf16 mma.sync projection, double-buffered (round-11 proven) ----------------
#define STG 16384   // 128 rows x 128 B per stage tile

__global__ __launch_bounds__(256, 2)
void proj_mma_kernel() {
    extern __shared__ char dsm[];
    uint32_t sb = smem_u32(dsm);
    int n0   = blockIdx.x * 128;
    int row0 = blockIdx.y * 128;
    int tid  = threadIdx.x;
    int wid  = tid >> 5, lane = tid & 31;
    int warp_m = wid >> 2, warp_n = wid & 3;
    int mb = warp_m * 64, nb = warp_n * 32;
    int grp = lane >> 2, q = lane & 3;
    int lr = tid >> 1, lh = tid & 1;

    float acc[4][4][4];
#pragma unroll
    for (int f = 0; f < 4; f++)
#pragma unroll
        for (int g = 0; g < 4; g++)
#pragma unroll
            for (int c = 0; c < 4; c++) acc[f][g][c] = 0.f;

    auto issue = [&](int s, int buf) {
        const char* srcA = (const char*)g_xh  + (size_t)(row0 + lr) * 1024 + s * 128 + lh * 64;
        const char* srcB = (const char*)g_wth + (size_t)(n0   + lr) * 1024 + s * 128 + lh * 64;
        uint32_t dA = sb + buf * STG       + lr * 128 + lh * 64;
        uint32_t dB = sb + (2 + buf) * STG + lr * 128 + lh * 64;
#pragma unroll
        for (int gi = 0; gi < 4; gi++) {
            cpasync16(dA + gi * 16, srcA + gi * 16);
            cpasync16(dB + gi * 16, srcB + gi * 16);
        }
    };

    issue(0, 0);
    CP_COMMIT();

    int buf = 0;
    for (int s = 0; s < 8; s++) {
        CP_WAIT0();
        __syncthreads();
        if (s < 7) { issue(s + 1, buf ^ 1); CP_COMMIT(); }

        const char* As = dsm + buf * STG;
        const char* Bs = dsm + (2 + buf) * STG;
#pragma unroll
        for (int c = 0; c < 4; c++) {
            uint2 bfr[4];
#pragma unroll
            for (int g = 0; g < 4; g++) {
                int rn = nb + g * 8 + grp;
                bfr[g] = *(const uint2*)(Bs + rn * 128 + ((c + rn) & 3) * 32 + q * 8);
            }
#pragma unroll
            for (int f = 0; f < 4; f++) {
                int r0 = mb + f * 16 + grp;
                int r1 = r0 + 8;
                uint2 aa = *(const uint2*)(As + r0 * 128 + ((c + r0) & 3) * 32 + q * 8);
                uint2 ab = *(const uint2*)(As + r1 * 128 + ((c + r1) & 3) * 32 + q * 8);
#pragma unroll
                for (int g = 0; g < 4; g++) {
                    asm volatile(
                        "mma.sync.aligned.m16n8k16.row.col.f32.bf16.bf16.f32 "
                        "{%0,%1,%2,%3}, {%4,%5,%6,%7}, {%8,%9}, {%0,%1,%2,%3};"
                        : "+f"(acc[f][g][0]), "+f"(acc[f][g][1]),
                          "+f"(acc[f][g][2]), "+f"(acc[f][g][3])
                        : "r"(aa.x), "r"(ab.x), "r"(aa.y), "r"(ab.y),
                          "r"(bfr[g].x), "r"(bfr[g].y));
                }
            }
        }
        buf ^= 1;
    }

    __nv_bfloat16* kh = (__nv_bfloat16*)g_k;
    __nv_bfloat16* vh = (__nv_bfloat16*)g_v;
#pragma unroll
    for (int f = 0; f < 4; f++) {
        int r0g = row0 + mb + f * 16 + grp;
        int r1g = r0g + 8;
        float m0 = g_stats[r0g * 2], s0 = g_stats[r0g * 2 + 1];
        float m1 = g_stats[r1g * 2], s1 = g_stats[r1g * 2 + 1];
        float mr0 = m0 * s0, mr1 = m1 * s1;
#pragma unroll
        for (int g = 0; g < 4; g++) {
            int nglob = n0 + nb + g * 8 + q * 2;
            float ws0 = g_wsum[nglob], ws1 = g_wsum[nglob + 1];
            __nv_bfloat162 o0 = __floats2bfloat162_rn(
                s0 * acc[f][g][0] - mr0 * ws0, s0 * acc[f][g][1] - mr0 * ws1);
            __nv_bfloat162 o1 = __floats2bfloat162_rn(
                s1 * acc[f][g][2] - mr1 * ws0, s1 * acc[f][g][3] - mr1 * ws1);
            if (nglob < 256) {
                *(__nv_bfloat162*)(kh + (size_t)r0g * 256 + nglob) = o0;
                *(__nv_bfloat162*)(kh + (size_t)r1g * 256 + nglob) = o1;
            } else {
                *(__nv_bfloat162*)(vh + (size_t)r0g * 256 + nglob - 256) = o0;
                *(__nv_bfloat162*)(vh + (size_t)r1g * 256 + nglob - 256) = o1;
            }
        }
    }
}

// ---------------- block LayerNorm over 256 (blockDim=256) ----------------
__device__ __forceinline__ float block_ln256(float v) {
    __shared__ float red[66];
    float s = v, s2 = v * v;
    int lane = threadIdx.x & 31, warp = threadIdx.x >> 5;
#pragma unroll
    for (int off = 16; off; off >>= 1) {
        s  += __shfl_down_sync(0xffffffffu, s,  off);
        s2 += __shfl_down_sync(0xffffffffu, s2, off);
    }
    if (!lane) { red[warp] = s; red[32 + warp] = s2; }
    __syncthreads();
    if (threadIdx.x == 0) {
        float ts = 0.f, t2 = 0.f;
#pragma unroll
        for (int i = 0; i < 8; i++) { ts += red[i]; t2 += red[32 + i]; }
        float m   = ts * (1.f / 256.f);
        float var = t2 * (1.f / 256.f) - m * m;
        red[64] = m;
        red[65] = rsqrtf(var + 1e-5f);
    }
    __syncthreads();
    return (v - red[64]) * red[65];
}

// ---------------- slots LN + q = s_ln @ Wq + zero accumulators (round-11) ----------------
__global__ void slot_ln_q_kernel(const float* __restrict__ Wq) {
    __shared__ float sln[256];
    int row = blockIdx.x, t = threadIdx.x;
    float v  = g_slots[row * 256 + t];
    float nv = block_ln256(v);
    g_sln[row * 256 + t] = nv;
    sln[t] = nv;
    g_upd[row * 256 + t] = 0.f;
    if (t == 0) g_colsum[row] = 0.f;
    __syncthreads();
    float a0 = 0.f, a1 = 0.f, a2 = 0.f, a3 = 0.f;
#pragma unroll 2
    for (int k = 0; k < 256; k += 4) {
        a0 += sln[k]     * Wq[(k)     * 256 + t];
        a1 += sln[k + 1] * Wq[(k + 1) * 256 + t];
        a2 += sln[k + 2] * Wq[(k + 2) * 256 + t];
        a3 += sln[k + 3] * Wq[(k + 3) * 256 + t];
    }
    g_q[row * 256 + t] = (a0 + a1) + (a2 + a3);
}

// ---------------- fused attention + updates (bf16 k/v, round-11 verbatim) ----------------
__global__ __launch_bounds__(256)
void attn_upd_kernel() {
    __shared__ __align__(16) float qs[2048];
    __shared__ float ps[128 * 8];
    int b  = blockIdx.y;
    int n0 = blockIdx.x * 128;
    int tid = threadIdx.x;
    int warp = tid >> 5, lane = tid & 31;
    const __nv_bfloat16* kh = (const __nv_bfloat16*)g_k;
    const __nv_bfloat16* vh = (const __nv_bfloat16*)g_v;

    for (int i = tid; i < 2048; i += 256) qs[i] = g_q[(size_t)b * 2048 + i];
    __syncthreads();

    const float scale = 0.0625f;
    float csum[8] = {};
#pragma unroll
    for (int g = 0; g < 4; g++) {
        int nb = warp * 16 + g * 4;
        const uint32_t* kp = (const uint32_t*)(kh + ((size_t)(b * Nv + n0 + nb)) * 256);
        float part[4][8] = {};
#pragma unroll
        for (int j = 0; j < 4; j++) {
            int pi = lane + 32 * j;
            float2 kv[4];
#pragma unroll
            for (int i = 0; i < 4; i++)
                kv[i] = __bfloat1622float2(*(const __nv_bfloat162*)&kp[i * 128 + pi]);
#pragma unroll
            for (int s = 0; s < 8; s++) {
                float2 qv = *(const float2*)(qs + s * 256 + 2 * pi);
#pragma unroll
                for (int i = 0; i < 4; i++)
                    part[i][s] += kv[i].x * qv.x + kv[i].y * qv.y;
            }
        }
#pragma unroll
        for (int i = 0; i < 4; i++)
#pragma unroll
            for (int s = 0; s < 8; s++)
#pragma unroll
                for (int off = 16; off; off >>= 1)
                    part[i][s] += __shfl_down_sync(0xffffffffu, part[i][s], off);
        if (lane == 0) {
#pragma unroll
            for (int i = 0; i < 4; i++) {
                float m = -1e30f;
#pragma unroll
                for (int s = 0; s < 8; s++) m = fmaxf(m, part[i][s] * scale);
                float e[8], sum = 0.f;
#pragma unroll
                for (int s = 0; s < 8; s++) { e[s] = __expf(part[i][s] * scale - m); sum += e[s]; }
                float inv = 1.f / sum;
                int nl = warp * 16 + g * 4 + i;
#pragma unroll
                for (int s = 0; s < 8; s++) {
                    float p = e[s] * inv + 1e-8f;
                    ps[nl * 8 + s] = p;
                    csum[s] += p;
                }
            }
        }
    }
    if (lane == 0) {
#pragma unroll
        for (int s = 0; s < 8; s++) atomicAdd(&g_colsum[b * 8 + s], csum[s]);
    }
    __syncthreads();

    int d = tid;
    float acc[8] = {};
    const __nv_bfloat16* vb = vh + ((size_t)(b * Nv + n0)) * 256;
#pragma unroll 4
    for (int n = 0; n < 128; n++) {
        float vv = __bfloat162float(vb[(size_t)n * 256 + d]);
#pragma unroll
        for (int s = 0; s < 8; s++) acc[s] += ps[n * 8 + s] * vv;
    }
#pragma unroll
    for (int s = 0; s < 8; s++) atomicAdd(&g_upd[(b * 8 + s) * 256 + d], acc[s]);
}

// ---------------- merged GRU gate GEMMs (round-11 verbatim) ----------------
__global__ __launch_bounds__(256)
void gru_gemm_kernel(const float* __restrict__ wih, const float* __restrict__ whh,
                     const float* __restrict__ bih, const float* __restrict__ bhh) {
    __shared__ float As[8 * 68];
    __shared__ float Bs[8 * 68];
    int path = blockIdx.x / 12;
    int bxl  = blockIdx.x - path * 12;
    const float* A    = path ? g_sln : g_upd;
    const float* Bm   = path ? whh   : wih;
    const float* bias = path ? bhh   : bih;
    float* C          = path ? g_gh  : g_gx;
    const int N = 768, K = 256;
    int bm = blockIdx.y * 64, bn = bxl * 64;
    int tid = threadIdx.x;
    int ty = tid >> 4, tx = tid & 15;

    float inv = 1.f;
    int arow = bm + (tid >> 1);
    if (tid < 128 && path == 0) inv = 1.f / g_colsum[arow];

    float acc[4][4] = {};
    for (int k0 = 0; k0 < K; k0 += 8) {
        if (tid < 128) {
            int row = tid >> 1, part = tid & 1;
            float4 av = *(const float4*)(A + (size_t)(bm + row) * K + k0 + part * 4);
            int kk = part * 4;
            As[(kk + 0) * 68 + row] = av.x * inv;
            As[(kk + 1) * 68 + row] = av.y * inv;
            As[(kk + 2) * 68 + row] = av.z * inv;
            As[(kk + 3) * 68 + row] = av.w * inv;
        } else {
            int t2 = tid - 128;
            int n = t2 >> 1, part = t2 & 1;
            float4 bv = *(const float4*)(Bm + (size_t)(bn + n) * K + k0 + part * 4);
            int kk = part * 4;
            Bs[(kk + 0) * 68 + n] = bv.x;
            Bs[(kk + 1) * 68 + n] = bv.y;
            Bs[(kk + 2) * 68 + n] = bv.z;
            Bs[(kk + 3) * 68 + n] = bv.w;
        }
        __syncthreads();
#pragma unroll
        for (int kk = 0; kk < 8; kk++) {
            float4 a = *(const float4*)(As + kk * 68 + ty * 4);
            float4 bq = *(const float4*)(Bs + kk * 68 + tx * 4);
            float av[4] = {a.x, a.y, a.z, a.w};
            float bw[4] = {bq.x, bq.y, bq.z, bq.w};
#pragma unroll
            for (int i = 0; i < 4; i++)
#pragma unroll
                for (int j = 0; j < 4; j++)
                    acc[i][j] += av[i] * bw[j];
        }
        __syncthreads();
    }
#pragma unroll
    for (int i = 0; i < 4; i++) {
        int r = bm + ty * 4 + i;
#pragma unroll
        for (int j = 0; j < 4; j++) {
            int c = bn + tx * 4 + j;
            C[(size_t)r * N + c] = acc[i][j] + bias[c];
        }
    }
}

// ---------------- small GEMM (round-11 verbatim) ----------------
template<bool RELU, bool ACCUM>
__global__ __launch_bounds__(256)
void gemm64_kernel(const float* __restrict__ A, const float* __restrict__ Bm,
                   const float* __restrict__ bias, float* __restrict__ C,
                   int M, int N, int K, float* __restrict__ out2) {
    __shared__ float As[8 * 68];
    __shared__ float Bs[8 * 68];
    int bm = blockIdx.y * 64, bn = blockIdx.x * 64;
    int tid = threadIdx.x;
    int ty = tid >> 4, tx = tid & 15;
    float acc[4][4] = {};
    for (int k0 = 0; k0 < K; k0 += 8) {
        if (tid < 128) {
            int row = tid >> 1, part = tid & 1;
            float4 av = *(const float4*)(A + (size_t)(bm + row) * K + k0 + part * 4);
            int kk = part * 4;
            As[(kk + 0) * 68 + row] = av.x;
            As[(kk + 1) * 68 + row] = av.y;
            As[(kk + 2) * 68 + row] = av.z;
            As[(kk + 3) * 68 + row] = av.w;
        } else {
            int t2 = tid - 128;
            int kk = t2 >> 4, q = t2 & 15;
            float4 bv = *(const float4*)(Bm + (size_t)(k0 + kk) * N + bn + q * 4);
            *(float4*)(Bs + kk * 68 + q * 4) = bv;
        }
        __syncthreads();
#pragma unroll
        for (int kk = 0; kk < 8; kk++) {
            float4 a = *(const float4*)(As + kk * 68 + ty * 4);
            float4 bq = *(const float4*)(Bs + kk * 68 + tx * 4);
            float av[4] = {a.x, a.y, a.z, a.w};
            float bw[4] = {bq.x, bq.y, bq.z, bq.w};
#pragma unroll
            for (int i = 0; i < 4; i++)
#pragma unroll
                for (int j = 0; j < 4; j++)
                    acc[i][j] += av[i] * bw[j];
        }
        __syncthreads();
    }
#pragma unroll
    for (int i = 0; i < 4; i++) {
        int r = bm + ty * 4 + i;
#pragma unroll
        for (int j = 0; j < 4; j++) {
            int c = bn + tx * 4 + j;
            float v = acc[i][j] + bias[c];
            if (RELU) v = fmaxf(v, 0.f);
            if (ACCUM) {
                float nv = C[(size_t)r * N + c] + v;
                C[(size_t)r * N + c] = nv;
                if (out2) out2[(size_t)r * N + c] = nv;
            } else {
                C[(size_t)r * N + c] = v;
            }
        }
    }
}

// ---------------- GRU combine + LN(y) fused (round-11 verbatim) ----------------
__global__ void gru_lny_kernel() {
    int row = blockIdx.x, t = threadIdx.x;
    int i = row * 256 + t;
    const float* gx = g_gx + row * 768;
    const float* gh = g_gh + row * 768;
    float r  = 1.f / (1.f + __expf(-(gx[t] + gh[t])));
    float z  = 1.f / (1.f + __expf(-(gx[256 + t] + gh[256 + t])));
    float nn = tanhf(gx[512 + t] + r * gh[512 + t]);
    float h  = (1.f - z) * nn + z * g_sln[i];
    g_slots[i] = h;
    g_y[i] = block_ln256(h);
}

// =====================================================================
extern "C" void kernel_launch(void* const* d_in, const int* in_sizes, int n_in,
                              void* d_out, int out_size) {
    (void)in_sizes; (void)n_in; (void)out_size;
    const float* inputs = (const float*)d_in[0];
    const float* noise  = (const float*)d_in[1];
    const float* Wk     = (const float*)d_in[2];
    const float* Wv     = (const float*)d_in[3];
    const float* Wq     = (const float*)d_in[4];
    const float* mu     = (const float*)d_in[5];
    const float* ls     = (const float*)d_in[6];
    const float* wih    = (const float*)d_in[7];
    const float* whh    = (const float*)d_in[8];
    const float* bih    = (const float*)d_in[9];
    const float* bhh    = (const float*)d_in[10];
    const float* w1     = (const float*)d_in[11];
    const float* b1     = (const float*)d_in[12];
    const float* w2     = (const float*)d_in[13];
    const float* b2     = (const float*)d_in[14];

    float *p_h1, *p_y, *p_slots;
    cudaGetSymbolAddress((void**)&p_h1,    g_h1);
    cudaGetSymbolAddress((void**)&p_y,     g_y);
    cudaGetSymbolAddress((void**)&p_slots, g_slots);

    cudaFuncSetAttribute(proj_mma_kernel,
                         cudaFuncAttributeMaxDynamicSharedMemorySize, 4 * STG);

    // launch order puts attn_upd at capture slot (4th launch)
    prep_kernel<<<296, 512>>>(Wk, Wv, noise, mu, ls, Wq);
    ln_stats_kernel<<<ROWSv / 8, 256>>>(inputs);
    proj_mma_kernel<<<dim3(4, 1024), 256, 4 * STG>>>();

    for (int it = 0; it < 3; it++) {
        attn_upd_kernel<<<dim3(32, 32), 256>>>();
        gru_gemm_kernel<<<dim3(24, 4), 256>>>(wih, whh, bih, bhh);
        gru_lny_kernel<<<256, 256>>>();
        gemm64_kernel<true,  false><<<dim3(8, 4), 256>>>(p_y,  w1, b1, p_h1,    256, 512, 256, nullptr);
        gemm64_kernel<false, true ><<<dim3(4, 4), 256>>>(p_h1, w2, b2, p_slots, 256, 256, 512,
                                                         (it == 2) ? (float*)d_out : nullptr);
        if (it < 2) slot_ln_q_kernel<<<256, 256>>>(Wq);
    }
}

// round 17
// speedup vs baseline: 1.5580x; 1.3162x over previous
#include <cuda_runtime.h>
#include <cuda_bf16.h>
#include <math.h>
#include <stdint.h>

// Problem constants
#define Bv    32
#define Nv    4096
#define INPv  512
#define ROWSv (Bv*Nv)   // 131072

// ---------------- scratch (static device globals; no allocs allowed) ----------------
__device__ __align__(16) float g_k[16777216];      // bf16 image [ROWS][256]
__device__ __align__(16) float g_v[16777216];      // bf16 image [ROWS][256]
__device__ __align__(16) uint16_t g_xh[67108864];  // bf16 image of X, MMA-swizzled [row][1024B]
__device__ __align__(16) uint16_t g_wth[262144];   // bf16 image of fused W^T [n][1024B]
__device__ __align__(16) float g_stats[262144];    // [ROWS][2] mean,rstd
__device__ __align__(16) float g_wsum[512];        // colsum of [Wk|Wv]
__device__ __align__(16) float g_slots[65536];
__device__ __align__(16) float g_sln[65536];
__device__ __align__(16) float g_q[65536];
__device__ __align__(16) float g_upd[65536];
__device__ __align__(16) float g_colsum[256];
__device__ __align__(16) float g_gx[196608];       // [256][768]
__device__ __align__(16) float g_gh[196608];
__device__ __align__(16) float g_h1[131072];       // [256][512]
__device__ __align__(16) float g_y[65536];

__device__ __forceinline__ uint32_t smem_u32(const void* p) {
    uint32_t a;
    asm("{ .reg .u64 t; cvta.to.shared.u64 t, %1; cvt.u32.u64 %0, t; }" : "=r"(a) : "l"(p));
    return a;
}
__device__ __forceinline__ void cpasync16(uint32_t d, const void* g) {
    asm volatile("cp.async.cg.shared.global [%0], [%1], 16;" :: "r"(d), "l"(g));
}
#define CP_COMMIT() asm volatile("cp.async.commit_group;" ::: "memory")
#define CP_WAIT0()  asm volatile("cp.async.wait_group 0;" ::: "memory")

__device__ __forceinline__ uint32_t pack_bf16x2(float lo, float hi) {
    uint32_t r;
    asm("cvt.rn.bf16x2.f32 %0, %1, %2;" : "=r"(r) : "f"(hi), "f"(lo));
    return r;
}

// image byte offset within a row for element k (k-pair permute + region rotation by row)
__device__ __forceinline__ int img_off(int k, int row) {
    int bblk = k >> 6;
    int c    = (k >> 4) & 3;
    int kk   = k & 15;
    int p    = kk >> 1;
    int slot = ((p & 3) << 1) | (p >> 2);
    int reg  = (c + row) & 3;
    return bblk * 128 + reg * 32 + slot * 4 + (kk & 1) * 2;
}

// ---------------- row LN over 8 rows x 256 (512 threads), src/dst in smem ----------------
__device__ __forceinline__ void row_ln8(const float* src, float* dst, float* s_red, int t) {
    int r = t >> 6, l64 = t & 63;
    float s = 0.f, s2 = 0.f;
#pragma unroll
    for (int j = 0; j < 4; j++) {
        float v = src[r * 256 + l64 + 64 * j];
        s += v; s2 += v * v;
    }
#pragma unroll
    for (int off = 16; off; off >>= 1) {
        s  += __shfl_down_sync(0xffffffffu, s,  off);
        s2 += __shfl_down_sync(0xffffffffu, s2, off);
    }
    int w = t >> 5;
    if ((t & 31) == 0) { s_red[w * 2] = s; s_red[w * 2 + 1] = s2; }
    __syncthreads();
    if (t < 8) {
        float ts = s_red[4 * t]     + s_red[4 * t + 2];
        float t2 = s_red[4 * t + 1] + s_red[4 * t + 3];
        float m = ts * (1.f / 256.f), var = t2 * (1.f / 256.f) - m * m;
        s_red[32 + 2 * t]     = m;
        s_red[32 + 2 * t + 1] = rsqrtf(var + 1e-5f);
    }
    __syncthreads();
    for (int i = t; i < 2048; i += 512) {
        int rr = i >> 8;
        dst[i] = (src[i] - s_red[32 + 2 * rr]) * s_red[33 + 2 * rr];
    }
    __syncthreads();
}

// q = sln @ Wq, sln in smem; store sln; zero accumulators (512 threads)
__device__ __forceinline__ void q_and_store(const float* s_sln, const float* __restrict__ Wq,
                                            int b, int t) {
    for (int i = t; i < 2048; i += 512) g_sln[b * 2048 + i] = s_sln[i];
    int c = t & 255, rg = t >> 8;
    float acc[4] = {0.f, 0.f, 0.f, 0.f};
    for (int k = 0; k < 256; k += 4) {
        float w0 = Wq[(k + 0) * 256 + c];
        float w1v = Wq[(k + 1) * 256 + c];
        float w2v = Wq[(k + 2) * 256 + c];
        float w3 = Wq[(k + 3) * 256 + c];
#pragma unroll
        for (int i = 0; i < 4; i++) {
            const float4 a = *(const float4*)(s_sln + (rg * 4 + i) * 256 + k);
            acc[i] += a.x * w0 + a.y * w1v + a.z * w2v + a.w * w3;
        }
    }
#pragma unroll
    for (int i = 0; i < 4; i++)
        g_q[b * 2048 + (rg * 4 + i) * 256 + c] = acc[i];
    for (int i = t; i < 2048; i += 512) g_upd[b * 2048 + i] = 0.f;
    if (t < 8) g_colsum[b * 8 + t] = 0.f;
}

// ---------------- prep: W transpose->bf16 image, wsum, slots init+LN+q (one launch) ----------------
__global__ __launch_bounds__(512)
void prep_kernel(const float* __restrict__ Wk, const float* __restrict__ Wv,
                 const float* __restrict__ noise, const float* __restrict__ mu,
                 const float* __restrict__ ls, const float* __restrict__ Wq) {
    __shared__ __align__(16) float sbuf[4160];
    int blk = blockIdx.x, t = threadIdx.x;
    if (blk < 256) {
        float* tt = sbuf;                 // [32][33]
        int n0 = (blk >> 4) * 32, k0 = (blk & 15) * 32;
        const float* W = (n0 < 256) ? Wk : Wv;
        int col0 = n0 & 255;
        int tx = t & 31, ty = t >> 5;     // ty 0..15
#pragma unroll
        for (int j = 0; j < 2; j++) {
            int k = k0 + ty + 16 * j;
            tt[(ty + 16 * j) * 33 + tx] = W[(size_t)k * 256 + col0 + tx];
        }
        __syncthreads();
#pragma unroll
        for (int j = 0; j < 2; j++) {
            int n = n0 + ty + 16 * j;
            int k = k0 + tx;
            __nv_bfloat16 h = __float2bfloat16(tt[tx * 33 + ty + 16 * j]);
            g_wth[(size_t)n * 512 + (img_off(k, n) >> 1)] = *(uint16_t*)&h;
        }
    } else if (blk < 264) {
        int c0 = (blk - 256) * 64;
        int col = t & 63, part = t >> 6;
        const float* W = (c0 < 256) ? Wk : Wv;
        int cc = (c0 & 255) + col;
        float s = 0.f;
        for (int k = part * 64; k < part * 64 + 64; k++) s += W[k * 256 + cc];
        sbuf[part * 64 + col] = s;
        __syncthreads();
        if (t < 64) {
            float acc = 0.f;
#pragma unroll
            for (int p = 0; p < 8; p++) acc += sbuf[p * 64 + t];
            g_wsum[c0 + t] = acc;
        }
    } else {
        float* s_h   = sbuf;
        float* s_sln = sbuf + 2048;
        float* s_red = sbuf + 4096;
        int b = blk - 264;
        for (int i = t; i < 2048; i += 512) {
            int d = i & 255;
            s_h[i] = mu[d] + __expf(ls[d]) * noise[b * 2048 + i];
        }
        __syncthreads();
        row_ln8(s_h, s_sln, s_red, t);
        q_and_store(s_sln, Wq, b, t);
    }
}

// ---------------- LN stats + bf16 swizzled image of X ----------------
__global__ void ln_stats_kernel(const float* __restrict__ X) {
    __shared__ __align__(16) uint16_t img[8][512];
    int warp = threadIdx.x >> 5, lane = threadIdx.x & 31;
    int row  = blockIdx.x * 8 + warp;
    const float* xr = X + (size_t)row * INPv;
    float4 v[4];
    float s = 0.f, s2 = 0.f;
#pragma unroll
    for (int j = 0; j < 4; j++) {
        v[j] = *(const float4*)(xr + lane * 4 + 128 * j);
        s  += v[j].x + v[j].y + v[j].z + v[j].w;
        s2 += v[j].x * v[j].x + v[j].y * v[j].y + v[j].z * v[j].z + v[j].w * v[j].w;
    }
#pragma unroll
    for (int off = 16; off; off >>= 1) {
        s  += __shfl_down_sync(0xffffffffu, s,  off);
        s2 += __shfl_down_sync(0xffffffffu, s2, off);
    }
    if (!lane) {
        float m   = s * (1.f / INPv);
        float var = s2 * (1.f / INPv) - m * m;
        g_stats[row * 2]     = m;
        g_stats[row * 2 + 1] = rsqrtf(var + 1e-5f);
    }
#pragma unroll
    for (int j = 0; j < 4; j++) {
        int k0 = lane * 4 + 128 * j;
        float vals[4] = {v[j].x, v[j].y, v[j].z, v[j].w};
#pragma unroll
        for (int t = 0; t < 2; t++) {
            int k = k0 + 2 * t;
            __nv_bfloat162 h2 = __floats2bfloat162_rn(vals[2 * t], vals[2 * t + 1]);
            *(uint32_t*)((char*)img[warp] + img_off(k, row)) = *(uint32_t*)&h2;
        }
    }
    __syncwarp();
    uint4* srcp = (uint4*)img[warp];
    uint4* dstp = (uint4*)(g_xh + (size_t)row * 512);
    dstp[lane]      = srcp[lane];
    dstp[lane + 32] = srcp[lane + 32];
}

// ---------------- bf16 mma.sync projection, double-buffered (proven) ----------------
#define STG 16384   // 128 rows x 128 B per stage tile

__global__ __launch_bounds__(256, 2)
void proj_mma_kernel() {
    extern __shared__ char dsm[];
    uint32_t sb = smem_u32(dsm);
    int n0   = blockIdx.x * 128;
    int row0 = blockIdx.y * 128;
    int tid  = threadIdx.x;
    int wid  = tid >> 5, lane = tid & 31;
    int warp_m = wid >> 2, warp_n = wid & 3;
    int mb = warp_m * 64, nb = warp_n * 32;
    int grp = lane >> 2, q = lane & 3;
    int lr = tid >> 1, lh = tid & 1;

    float acc[4][4][4];
#pragma unroll
    for (int f = 0; f < 4; f++)
#pragma unroll
        for (int g = 0; g < 4; g++)
#pragma unroll
            for (int c = 0; c < 4; c++) acc[f][g][c] = 0.f;

    auto issue = [&](int s, int buf) {
        const char* srcA = (const char*)g_xh  + (size_t)(row0 + lr) * 1024 + s * 128 + lh * 64;
        const char* srcB = (const char*)g_wth + (size_t)(n0   + lr) * 1024 + s * 128 + lh * 64;
        uint32_t dA = sb + buf * STG       + lr * 128 + lh * 64;
        uint32_t dB = sb + (2 + buf) * STG + lr * 128 + lh * 64;
#pragma unroll
        for (int gi = 0; gi < 4; gi++) {
            cpasync16(dA + gi * 16, srcA + gi * 16);
            cpasync16(dB + gi * 16, srcB + gi * 16);
        }
    };

    issue(0, 0);
    CP_COMMIT();

    int buf = 0;
    for (int s = 0; s < 8; s++) {
        CP_WAIT0();
        __syncthreads();
        if (s < 7) { issue(s + 1, buf ^ 1); CP_COMMIT(); }

        const char* As = dsm + buf * STG;
        const char* Bs = dsm + (2 + buf) * STG;
#pragma unroll
        for (int c = 0; c < 4; c++) {
            uint2 bfr[4];
#pragma unroll
            for (int g = 0; g < 4; g++) {
                int rn = nb + g * 8 + grp;
                bfr[g] = *(const uint2*)(Bs + rn * 128 + ((c + rn) & 3) * 32 + q * 8);
            }
#pragma unroll
            for (int f = 0; f < 4; f++) {
                int r0 = mb + f * 16 + grp;
                int r1 = r0 + 8;
                uint2 aa = *(const uint2*)(As + r0 * 128 + ((c + r0) & 3) * 32 + q * 8);
                uint2 ab = *(const uint2*)(As + r1 * 128 + ((c + r1) & 3) * 32 + q * 8);
#pragma unroll
                for (int g = 0; g < 4; g++) {
                    asm volatile(
                        "mma.sync.aligned.m16n8k16.row.col.f32.bf16.bf16.f32 "
                        "{%0,%1,%2,%3}, {%4,%5,%6,%7}, {%8,%9}, {%0,%1,%2,%3};"
                        : "+f"(acc[f][g][0]), "+f"(acc[f][g][1]),
                          "+f"(acc[f][g][2]), "+f"(acc[f][g][3])
                        : "r"(aa.x), "r"(ab.x), "r"(aa.y), "r"(ab.y),
                          "r"(bfr[g].x), "r"(bfr[g].y));
                }
            }
        }
        buf ^= 1;
    }

    __nv_bfloat16* kh = (__nv_bfloat16*)g_k;
    __nv_bfloat16* vh = (__nv_bfloat16*)g_v;
#pragma unroll
    for (int f = 0; f < 4; f++) {
        int r0g = row0 + mb + f * 16 + grp;
        int r1g = r0g + 8;
        float m0 = g_stats[r0g * 2], s0 = g_stats[r0g * 2 + 1];
        float m1 = g_stats[r1g * 2], s1 = g_stats[r1g * 2 + 1];
        float mr0 = m0 * s0, mr1 = m1 * s1;
#pragma unroll
        for (int g = 0; g < 4; g++) {
            int nglob = n0 + nb + g * 8 + q * 2;
            float ws0 = g_wsum[nglob], ws1 = g_wsum[nglob + 1];
            __nv_bfloat162 o0 = __floats2bfloat162_rn(
                s0 * acc[f][g][0] - mr0 * ws0, s0 * acc[f][g][1] - mr0 * ws1);
            __nv_bfloat162 o1 = __floats2bfloat162_rn(
                s1 * acc[f][g][2] - mr1 * ws0, s1 * acc[f][g][3] - mr1 * ws1);
            if (nglob < 256) {
                *(__nv_bfloat162*)(kh + (size_t)r0g * 256 + nglob) = o0;
                *(__nv_bfloat162*)(kh + (size_t)r1g * 256 + nglob) = o1;
            } else {
                *(__nv_bfloat162*)(vh + (size_t)r0g * 256 + nglob - 256) = o0;
                *(__nv_bfloat162*)(vh + (size_t)r1g * 256 + nglob - 256) = o1;
            }
        }
    }
}

// ---------------- block LayerNorm over 256 (blockDim=256) ----------------
__device__ __forceinline__ float block_ln256(float v) {
    __shared__ float red[66];
    float s = v, s2 = v * v;
    int lane = threadIdx.x & 31, warp = threadIdx.x >> 5;
#pragma unroll
    for (int off = 16; off; off >>= 1) {
        s  += __shfl_down_sync(0xffffffffu, s,  off);
        s2 += __shfl_down_sync(0xffffffffu, s2, off);
    }
    if (!lane) { red[warp] = s; red[32 + warp] = s2; }
    __syncthreads();
    if (threadIdx.x == 0) {
        float ts = 0.f, t2 = 0.f;
#pragma unroll
        for (int i = 0; i < 8; i++) { ts += red[i]; t2 += red[32 + i]; }
        float m   = ts * (1.f / 256.f);
        float var = t2 * (1.f / 256.f) - m * m;
        red[64] = m;
        red[65] = rsqrtf(var + 1e-5f);
    }
    __syncthreads();
    return (v - red[64]) * red[65];
}

// ---------------- slots LN + q + zero accumulators ----------------
__global__ void slot_ln_q_kernel(const float* __restrict__ Wq) {
    __shared__ float sln[256];
    int row = blockIdx.x, t = threadIdx.x;
    float v  = g_slots[row * 256 + t];
    float nv = block_ln256(v);
    g_sln[row * 256 + t] = nv;
    sln[t] = nv;
    g_upd[row * 256 + t] = 0.f;
    if (t == 0) g_colsum[row] = 0.f;
    __syncthreads();
    float a0 = 0.f, a1 = 0.f, a2 = 0.f, a3 = 0.f;
#pragma unroll 2
    for (int k = 0; k < 256; k += 4) {
        a0 += sln[k]     * Wq[(k)     * 256 + t];
        a1 += sln[k + 1] * Wq[(k + 1) * 256 + t];
        a2 += sln[k + 2] * Wq[(k + 2) * 256 + t];
        a3 += sln[k + 3] * Wq[(k + 3) * 256 + t];
    }
    g_q[row * 256 + t] = (a0 + a1) + (a2 + a3);
}

// ---------------- attention via MMA (phase1) + vectorized p^T v (phase2) ----------------
// grid (32 n-chunks, 32 b), 256 threads. Warp w: rows w*16..w*16+15 of this chunk.
// k-remap: within 16-k chunk j, lane q owns k = 16j+4q..+3 (A and B consistent).
__global__ __launch_bounds__(256)
void attn_upd_kernel() {
    __shared__ __align__(16) float qs[2048];   // [8 slots][256]
    __shared__ __align__(16) float ps[1024];   // [128 rows][8 slots]
    int b  = blockIdx.y;
    int n0 = blockIdx.x * 128;
    int tid = threadIdx.x;
    int w = tid >> 5, lane = tid & 31;
    int grp = lane >> 2, q = lane & 3;
    const __nv_bfloat16* vh = (const __nv_bfloat16*)g_v;

    for (int i = tid; i < 2048; i += 256) qs[i] = g_q[(size_t)b * 2048 + i];
    __syncthreads();

    // ---- phase 1: logits via mma, softmax from C fragments ----
    // B fragments: slot n = grp, k per remap
    uint32_t bf[16][2];
#pragma unroll
    for (int j = 0; j < 16; j++) {
        const float* qp = qs + grp * 256 + 16 * j + 4 * q;
        float2 u = *(const float2*)(qp);
        float2 v2 = *(const float2*)(qp + 2);
        bf[j][0] = pack_bf16x2(u.x, u.y);
        bf[j][1] = pack_bf16x2(v2.x, v2.y);
    }
    const char* kb = (const char*)g_k;
    size_t rowA = (size_t)(b * Nv + n0 + w * 16 + grp) * 512;
    size_t rowB = rowA + 8 * 512;
    float c[4] = {0.f, 0.f, 0.f, 0.f};
#pragma unroll
    for (int j = 0; j < 16; j++) {
        uint2 a02 = *(const uint2*)(kb + rowA + 32 * j + 8 * q);
        uint2 a13 = *(const uint2*)(kb + rowB + 32 * j + 8 * q);
        asm volatile(
            "mma.sync.aligned.m16n8k16.row.col.f32.bf16.bf16.f32 "
            "{%0,%1,%2,%3}, {%4,%5,%6,%7}, {%8,%9}, {%0,%1,%2,%3};"
            : "+f"(c[0]), "+f"(c[1]), "+f"(c[2]), "+f"(c[3])
            : "r"(a02.x), "r"(a13.x), "r"(a02.y), "r"(a13.y),
              "r"(bf[j][0]), "r"(bf[j][1]));
    }
    // c0=(row grp, s 2q) c1=(grp, 2q+1) c2=(grp+8, 2q) c3=(grp+8, 2q+1)
    const float scale = 0.0625f;
    float l0 = c[0] * scale, l1 = c[1] * scale, l2 = c[2] * scale, l3 = c[3] * scale;
    float m0 = fmaxf(l0, l1), m1 = fmaxf(l2, l3);
    m0 = fmaxf(m0, __shfl_xor_sync(0xffffffffu, m0, 1));
    m0 = fmaxf(m0, __shfl_xor_sync(0xffffffffu, m0, 2));
    m1 = fmaxf(m1, __shfl_xor_sync(0xffffffffu, m1, 1));
    m1 = fmaxf(m1, __shfl_xor_sync(0xffffffffu, m1, 2));
    float e0 = __expf(l0 - m0), e1 = __expf(l1 - m0);
    float e2 = __expf(l2 - m1), e3 = __expf(l3 - m1);
    float s0 = e0 + e1, s1 = e2 + e3;
    s0 += __shfl_xor_sync(0xffffffffu, s0, 1);
    s0 += __shfl_xor_sync(0xffffffffu, s0, 2);
    s1 += __shfl_xor_sync(0xffffffffu, s1, 1);
    s1 += __shfl_xor_sync(0xffffffffu, s1, 2);
    float p00 = e0 / s0 + 1e-8f, p01 = e1 / s0 + 1e-8f;
    float p10 = e2 / s1 + 1e-8f, p11 = e3 / s1 + 1e-8f;
    int r0l = w * 16 + grp;
    *(float2*)(ps + r0l * 8 + 2 * q)       = make_float2(p00, p01);
    *(float2*)(ps + (r0l + 8) * 8 + 2 * q) = make_float2(p10, p11);
    // csum over rows: reduce over grp lanes (xor 4,8,16)
    float cs0 = p00 + p10, cs1 = p01 + p11;
#pragma unroll
    for (int off = 4; off < 32; off <<= 1) {
        cs0 += __shfl_xor_sync(0xffffffffu, cs0, off);
        cs1 += __shfl_xor_sync(0xffffffffu, cs1, off);
    }
    if (lane < 4) {
        atomicAdd(&g_colsum[b * 8 + 2 * lane],     cs0);
        atomicAdd(&g_colsum[b * 8 + 2 * lane + 1], cs1);
    }
    __syncthreads();

    // ---- phase 2: p^T v, 2 d per thread, n split in halves ----
    int half = tid >> 7;                 // 0/1
    int dl = (tid & 127) * 2;
    const __nv_bfloat16* vb = vh + ((size_t)(b * Nv + n0 + half * 64)) * 256;
    const float* psh = ps + half * 64 * 8;
    float acc[8][2];
#pragma unroll
    for (int s = 0; s < 8; s++) { acc[s][0] = 0.f; acc[s][1] = 0.f; }
#pragma unroll 4
    for (int n = 0; n < 64; n++) {
        float2 vv = __bfloat1622float2(*(const __nv_bfloat162*)(vb + (size_t)n * 256 + dl));
        float4 p0 = *(const float4*)(psh + n * 8);
        float4 p1 = *(const float4*)(psh + n * 8 + 4);
        acc[0][0] += p0.x * vv.x; acc[0][1] += p0.x * vv.y;
        acc[1][0] += p0.y * vv.x; acc[1][1] += p0.y * vv.y;
        acc[2][0] += p0.z * vv.x; acc[2][1] += p0.z * vv.y;
        acc[3][0] += p0.w * vv.x; acc[3][1] += p0.w * vv.y;
        acc[4][0] += p1.x * vv.x; acc[4][1] += p1.x * vv.y;
        acc[5][0] += p1.y * vv.x; acc[5][1] += p1.y * vv.y;
        acc[6][0] += p1.z * vv.x; acc[6][1] += p1.z * vv.y;
        acc[7][0] += p1.w * vv.x; acc[7][1] += p1.w * vv.y;
    }
#pragma unroll
    for (int s = 0; s < 8; s++) {
        atomicAdd(&g_upd[(b * 8 + s) * 256 + dl],     acc[s][0]);
        atomicAdd(&g_upd[(b * 8 + s) * 256 + dl + 1], acc[s][1]);
    }
}

// ---------------- merged GRU gate GEMMs ----------------
__global__ __launch_bounds__(256)
void gru_gemm_kernel(const float* __restrict__ wih, const float* __restrict__ whh,
                     const float* __restrict__ bih, const float* __restrict__ bhh) {
    __shared__ float As[8 * 68];
    __shared__ float Bs[8 * 68];
    int path = blockIdx.x / 12;
    int bxl  = blockIdx.x - path * 12;
    const float* A    = path ? g_sln : g_upd;
    const float* Bm   = path ? whh   : wih;
    const float* bias = path ? bhh   : bih;
    float* C          = path ? g_gh  : g_gx;
    const int N = 768, K = 256;
    int bm = blockIdx.y * 64, bn = bxl * 64;
    int tid = threadIdx.x;
    int ty = tid >> 4, tx = tid & 15;

    float inv = 1.f;
    int arow = bm + (tid >> 1);
    if (tid < 128 && path == 0) inv = 1.f / g_colsum[arow];

    float acc[4][4] = {};
    for (int k0 = 0; k0 < K; k0 += 8) {
        if (tid < 128) {
            int row = tid >> 1, part = tid & 1;
            float4 av = *(const float4*)(A + (size_t)(bm + row) * K + k0 + part * 4);
            int kk = part * 4;
            As[(kk + 0) * 68 + row] = av.x * inv;
            As[(kk + 1) * 68 + row] = av.y * inv;
            As[(kk + 2) * 68 + row] = av.z * inv;
            As[(kk + 3) * 68 + row] = av.w * inv;
        } else {
            int t2 = tid - 128;
            int n = t2 >> 1, part = t2 & 1;
            float4 bv = *(const float4*)(Bm + (size_t)(bn + n) * K + k0 + part * 4);
            int kk = part * 4;
            Bs[(kk + 0) * 68 + n] = bv.x;
            Bs[(kk + 1) * 68 + n] = bv.y;
            Bs[(kk + 2) * 68 + n] = bv.z;
            Bs[(kk + 3) * 68 + n] = bv.w;
        }
        __syncthreads();
#pragma unroll
        for (int kk = 0; kk < 8; kk++) {
            float4 a = *(const float4*)(As + kk * 68 + ty * 4);
            float4 bq = *(const float4*)(Bs + kk * 68 + tx * 4);
            float av[4] = {a.x, a.y, a.z, a.w};
            float bw[4] = {bq.x, bq.y, bq.z, bq.w};
#pragma unroll
            for (int i = 0; i < 4; i++)
#pragma unroll
                for (int j = 0; j < 4; j++)
                    acc[i][j] += av[i] * bw[j];
        }
        __syncthreads();
    }
#pragma unroll
    for (int i = 0; i < 4; i++) {
        int r = bm + ty * 4 + i;
#pragma unroll
        for (int j = 0; j < 4; j++) {
            int c = bn + tx * 4 + j;
            C[(size_t)r * N + c] = acc[i][j] + bias[c];
        }
    }
}

// ---------------- small GEMM ----------------
template<bool RELU, bool ACCUM>
__global__ __launch_bounds__(256)
void gemm64_kernel(const float* __restrict__ A, const float* __restrict__ Bm,
                   const float* __restrict__ bias, float* __restrict__ C,
                   int M, int N, int K, float* __restrict__ out2) {
    __shared__ float As[8 * 68];
    __shared__ float Bs[8 * 68];
    int bm = blockIdx.y * 64, bn = blockIdx.x * 64;
    int tid = threadIdx.x;
    int ty = tid >> 4, tx = tid & 15;
    float acc[4][4] = {};
    for (int k0 = 0; k0 < K; k0 += 8) {
        if (tid < 128) {
            int row = tid >> 1, part = tid & 1;
            float4 av = *(const float4*)(A + (size_t)(bm + row) * K + k0 + part * 4);
            int kk = part * 4;
            As[(kk + 0) * 68 + row] = av.x;
            As[(kk + 1) * 68 + row] = av.y;
            As[(kk + 2) * 68 + row] = av.z;
            As[(kk + 3) * 68 + row] = av.w;
        } else {
            int t2 = tid - 128;
            int kk = t2 >> 4, q = t2 & 15;
            float4 bv = *(const float4*)(Bm + (size_t)(k0 + kk) * N + bn + q * 4);
            *(float4*)(Bs + kk * 68 + q * 4) = bv;
        }
        __syncthreads();
#pragma unroll
        for (int kk = 0; kk < 8; kk++) {
            float4 a = *(const float4*)(As + kk * 68 + ty * 4);
            float4 bq = *(const float4*)(Bs + kk * 68 + tx * 4);
            float av[4] = {a.x, a.y, a.z, a.w};
            float bw[4] = {bq.x, bq.y, bq.z, bq.w};
#pragma unroll
            for (int i = 0; i < 4; i++)
#pragma unroll
                for (int j = 0; j < 4; j++)
                    acc[i][j] += av[i] * bw[j];
        }
        __syncthreads();
    }
#pragma unroll
    for (int i = 0; i < 4; i++) {
        int r = bm + ty * 4 + i;
#pragma unroll
        for (int j = 0; j < 4; j++) {
            int c = bn + tx * 4 + j;
            float v = acc[i][j] + bias[c];
            if (RELU) v = fmaxf(v, 0.f);
            if (ACCUM) {
                float nv = C[(size_t)r * N + c] + v;
                C[(size_t)r * N + c] = nv;
                if (out2) out2[(size_t)r * N + c] = nv;
            } else {
                C[(size_t)r * N + c] = v;
            }
        }
    }
}

// ---------------- GRU combine + LN(y) fused ----------------
__global__ void gru_lny_kernel() {
    int row = blockIdx.x, t = threadIdx.x;
    int i = row * 256 + t;
    const float* gx = g_gx + row * 768;
    const float* gh = g_gh + row * 768;
    float r  = 1.f / (1.f + __expf(-(gx[t] + gh[t])));
    float z  = 1.f / (1.f + __expf(-(gx[256 + t] + gh[256 + t])));
    float nn = tanhf(gx[512 + t] + r * gh[512 + t]);
    float h  = (1.f - z) * nn + z * g_sln[i];
    g_slots[i] = h;
    g_y[i] = block_ln256(h);
}

// =====================================================================
extern "C" void kernel_launch(void* const* d_in, const int* in_sizes, int n_in,
                              void* d_out, int out_size) {
    (void)in_sizes; (void)n_in; (void)out_size;
    const float* inputs = (const float*)d_in[0];
    const float* noise  = (const float*)d_in[1];
    const float* Wk     = (const float*)d_in[2];
    const float* Wv     = (const float*)d_in[3];
    const float* Wq     = (const float*)d_in[4];
    const float* mu     = (const float*)d_in[5];
    const float* ls     = (const float*)d_in[6];
    const float* wih    = (const float*)d_in[7];
    const float* whh    = (const float*)d_in[8];
    const float* bih    = (const float*)d_in[9];
    const float* bhh    = (const float*)d_in[10];
    const float* w1     = (const float*)d_in[11];
    const float* b1     = (const float*)d_in[12];
    const float* w2     = (const float*)d_in[13];
    const float* b2     = (const float*)d_in[14];

    float *p_h1, *p_y, *p_slots;
    cudaGetSymbolAddress((void**)&p_h1,    g_h1);
    cudaGetSymbolAddress((void**)&p_y,     g_y);
    cudaGetSymbolAddress((void**)&p_slots, g_slots);

    cudaFuncSetAttribute(proj_mma_kernel,
                         cudaFuncAttributeMaxDynamicSharedMemorySize, 4 * STG);

    // launch order keeps attn_upd at capture slot (4th launch)
    prep_kernel<<<296, 512>>>(Wk, Wv, noise, mu, ls, Wq);
    ln_stats_kernel<<<ROWSv / 8, 256>>>(inputs);
    proj_mma_kernel<<<dim3(4, 1024), 256, 4 * STG>>>();

    for (int it = 0; it < 3; it++) {
        attn_upd_kernel<<<dim3(32, 32), 256>>>();
        gru_gemm_kernel<<<dim3(24, 4), 256>>>(wih, whh, bih, bhh);
        gru_lny_kernel<<<256, 256>>>();
        gemm64_kernel<true,  false><<<dim3(8, 4), 256>>>(p_y,  w1, b1, p_h1,    256, 512, 256, nullptr);
        gemm64_kernel<false, true ><<<dim3(4, 4), 256>>>(p_h1, w2, b2, p_slots, 256, 256, 512,
                                                         (it == 2) ? (float*)d_out : nullptr);
        if (it < 2) slot_ln_q_kernel<<<256, 256>>>(Wq);
    }
}